// round 7
// baseline (speedup 1.0000x reference)
#include <cuda_runtime.h>
#include <cuda_bf16.h>
#include <cstdint>
#include <math.h>

#define LSEQ 2048
#define DIM  256
#define BATCH 8

#define KC 32          // bf16 k per chunk
#define PAD_STR 40     // smem row stride in elements (80B: conflict-free for ldmatrix)
#define TILE_B (128 * PAD_STR * 2)          // 10240 bytes per tile
#define STAGE_B (4 * TILE_B)                // Ah, Al, Bh, Bl
#define NSTAGE 3
#define SMEM_DYN (NSTAGE * STAGE_B)         // 3 stages = 122880 bytes
#define NTHR 512

// ============================ PTX helpers ====================================
__device__ __forceinline__ uint32_t smem_to_u32(const void* p) {
    uint32_t a;
    asm("{ .reg .u64 t; cvta.to.shared.u64 t, %1; cvt.u32.u64 %0, t; }"
        : "=r"(a) : "l"(p));
    return a;
}
__device__ __forceinline__ void cp_async16(uint32_t dst, const void* src) {
    asm volatile("cp.async.cg.shared.global [%0], [%1], 16;" :: "r"(dst), "l"(src));
}
#define CP_COMMIT() asm volatile("cp.async.commit_group;" ::: "memory")
#define CP_WAIT1()  asm volatile("cp.async.wait_group 1;" ::: "memory")

__device__ __forceinline__ void ldsm_x4(uint32_t addr, uint32_t* r) {
    asm volatile("ldmatrix.sync.aligned.m8n8.x4.shared.b16 {%0,%1,%2,%3}, [%4];"
                 : "=r"(r[0]), "=r"(r[1]), "=r"(r[2]), "=r"(r[3]) : "r"(addr));
}
__device__ __forceinline__ void mma_bf16(float* c, const uint32_t* a, const uint32_t* b) {
    asm volatile(
        "mma.sync.aligned.m16n8k16.row.col.f32.bf16.bf16.f32 "
        "{%0,%1,%2,%3}, {%4,%5,%6,%7}, {%8,%9}, {%0,%1,%2,%3};"
        : "+f"(c[0]), "+f"(c[1]), "+f"(c[2]), "+f"(c[3])
        : "r"(a[0]), "r"(a[1]), "r"(a[2]), "r"(a[3]), "r"(b[0]), "r"(b[1]));
}

// ============================ device scratch =================================
static __device__ __nv_bfloat16 g_c1_hi[(size_t)BATCH * LSEQ * DIM];
static __device__ __nv_bfloat16 g_c1_lo[(size_t)BATCH * LSEQ * DIM];
static __device__ __nv_bfloat16 g_c2_hi[(size_t)BATCH * LSEQ * DIM];
static __device__ __nv_bfloat16 g_c2_lo[(size_t)BATCH * LSEQ * DIM];
static __device__ __nv_bfloat16 g_c1t_hi[(size_t)BATCH * DIM * LSEQ];
static __device__ __nv_bfloat16 g_c1t_lo[(size_t)BATCH * DIM * LSEQ];
static __device__ __nv_bfloat16 g_wft_hi[(size_t)DIM * 4 * DIM];   // [n=256][k=1024]
static __device__ __nv_bfloat16 g_wft_lo[(size_t)DIM * 4 * DIM];
static __device__ float         g_scores[(size_t)BATCH * LSEQ * LSEQ];
static __device__ __nv_bfloat16 g_alpha_hi[(size_t)BATCH * LSEQ * LSEQ];
static __device__ __nv_bfloat16 g_alpha_lo[(size_t)BATCH * LSEQ * LSEQ];
static __device__ float         g_aug[(size_t)BATCH * LSEQ * DIM];
static __device__ __nv_bfloat16 g_z_hi[(size_t)BATCH * LSEQ * 4 * DIM];
static __device__ __nv_bfloat16 g_z_lo[(size_t)BATCH * LSEQ * 4 * DIM];
static __device__ float         g_gate[BATCH * LSEQ];

// ============================ prep kernels ===================================
__global__ __launch_bounds__(256) void k_prep_split(const float* __restrict__ c1,
                                                    const float* __restrict__ c2) {
    size_t i = (size_t)blockIdx.x * 256 + threadIdx.x;
    if (i < (size_t)BATCH * LSEQ * DIM) {
        float v = c1[i];
        __nv_bfloat16 h = __float2bfloat16(v);
        g_c1_hi[i] = h;
        g_c1_lo[i] = __float2bfloat16(v - __bfloat162float(h));
        v = c2[i];
        h = __float2bfloat16(v);
        g_c2_hi[i] = h;
        g_c2_lo[i] = __float2bfloat16(v - __bfloat162float(h));
    }
}

__global__ __launch_bounds__(256) void k_prep_t(const float* __restrict__ c1) {
    __shared__ float tile[32][33];
    const int b = blockIdx.z;
    const int j0 = blockIdx.x * 32, d0 = blockIdx.y * 32;
    const float* src = c1 + (size_t)b * LSEQ * DIM;
    const int tx = threadIdx.x, ty = threadIdx.y;  // block (32, 8)
#pragma unroll
    for (int r = 0; r < 32; r += 8)
        tile[ty + r][tx] = src[(size_t)(j0 + ty + r) * DIM + d0 + tx];
    __syncthreads();
#pragma unroll
    for (int r = 0; r < 32; r += 8) {
        float v = tile[tx][ty + r];
        __nv_bfloat16 h = __float2bfloat16(v);
        size_t o = (size_t)b * DIM * LSEQ + (size_t)(d0 + ty + r) * LSEQ + j0 + tx;
        g_c1t_hi[o] = h;
        g_c1t_lo[o] = __float2bfloat16(v - __bfloat162float(h));
    }
}

__global__ __launch_bounds__(256) void k_prep_wft(const float* __restrict__ Wf) {
    int i = blockIdx.x * 256 + threadIdx.x;  // i = n*1024 + k
    if (i < DIM * 4 * DIM) {
        int n = i >> 10, k = i & 1023;
        float v = Wf[(size_t)k * DIM + n];
        __nv_bfloat16 h = __float2bfloat16(v);
        g_wft_hi[i] = h;
        g_wft_lo[i] = __float2bfloat16(v - __bfloat162float(h));
    }
}

// ============================ GEMM mainloop ==================================
// Block tile 128x128, 16 warps, warp tile 32x32 (warp grid 4m x 4n).
// A: [m][k] row-major hi/lo; B: [n][k] row-major hi/lo (i.e. B^T).
// 3 passes: Ah*Bh + Ah*Bl + Al*Bh accumulated into fp32.
// 3-stage cp.async pipeline, single __syncthreads per chunk.
__device__ __forceinline__ void load_chunk(uint32_t sbase,
                                           const __nv_bfloat16* __restrict__ Ah,
                                           const __nv_bfloat16* __restrict__ Al,
                                           size_t aStr,
                                           const __nv_bfloat16* __restrict__ Bh,
                                           const __nv_bfloat16* __restrict__ Bl,
                                           size_t bStr, int kOff) {
    const int t = threadIdx.x;
    const int c = (t & 3) * 8;   // bf16 col within 32
    const int r = t >> 2;        // 0..127
    const uint32_t soff = (uint32_t)(r * PAD_STR + c) * 2;
    cp_async16(sbase + 0 * TILE_B + soff, Ah + (size_t)r * aStr + kOff + c);
    cp_async16(sbase + 1 * TILE_B + soff, Al + (size_t)r * aStr + kOff + c);
    cp_async16(sbase + 2 * TILE_B + soff, Bh + (size_t)r * bStr + kOff + c);
    cp_async16(sbase + 3 * TILE_B + soff, Bl + (size_t)r * bStr + kOff + c);
}

__device__ __forceinline__ void gemm_tile(const __nv_bfloat16* __restrict__ Ah,
                                          const __nv_bfloat16* __restrict__ Al,
                                          size_t aStr,
                                          const __nv_bfloat16* __restrict__ Bh,
                                          const __nv_bfloat16* __restrict__ Bl,
                                          size_t bStr, int nChunks, char* sm,
                                          float acc[2][4][4]) {
    const int t = threadIdx.x;
    const int w = t >> 5, lane = t & 31;
    const int wm = (w & 3) * 32;        // warp m offset
    const int wn = (w >> 2) * 32;       // warp n offset
    const uint32_t smb = smem_to_u32(sm);

#pragma unroll
    for (int mf = 0; mf < 2; mf++)
#pragma unroll
        for (int nf = 0; nf < 4; nf++)
#pragma unroll
            for (int e = 0; e < 4; e++) acc[mf][nf][e] = 0.f;

    // per-lane ldmatrix base offsets
    const int arow = wm + (lane & 15);
    const int acol = (lane >> 4) * 8;
    const int brow = wn + (lane & 7) + ((lane >> 4) ? 8 : 0);
    const int bcol = ((lane >> 3) & 1) * 8;

    // prologue: stages 0 and 1 (nChunks >= 2 always here)
    load_chunk(smb + 0 * STAGE_B, Ah, Al, aStr, Bh, Bl, bStr, 0);
    CP_COMMIT();
    load_chunk(smb + 1 * STAGE_B, Ah, Al, aStr, Bh, Bl, bStr, KC);
    CP_COMMIT();
    CP_WAIT1();        // stage 0 ready
    __syncthreads();

    int cur = 0;
    for (int kc = 0; kc < nChunks; kc++) {
        if (kc + 2 < nChunks) {
            int nxt = cur + 2; if (nxt >= NSTAGE) nxt -= NSTAGE;
            load_chunk(smb + (uint32_t)nxt * STAGE_B, Ah, Al, aStr, Bh, Bl, bStr,
                       (kc + 2) * KC);
        }
        CP_COMMIT();   // empty group on tail iterations keeps wait counts uniform

        const uint32_t s = (uint32_t)cur * STAGE_B;
        const uint32_t sah = smb + s + 0 * TILE_B;
        const uint32_t sal = smb + s + 1 * TILE_B;
        const uint32_t sbh = smb + s + 2 * TILE_B;
        const uint32_t sbl = smb + s + 3 * TILE_B;

#pragma unroll
        for (int ks = 0; ks < 2; ks++) {
            const int k0 = ks * 16;
            uint32_t ah[2][4], al[2][4], bh[2][4], bl[2][4];
#pragma unroll
            for (int mf = 0; mf < 2; mf++) {
                const uint32_t off = (uint32_t)((arow + mf * 16) * PAD_STR + acol + k0) * 2;
                ldsm_x4(sah + off, ah[mf]);
                ldsm_x4(sal + off, al[mf]);
            }
#pragma unroll
            for (int nb = 0; nb < 2; nb++) {
                const uint32_t off = (uint32_t)((brow + nb * 16) * PAD_STR + bcol + k0) * 2;
                ldsm_x4(sbh + off, bh[nb]);
                ldsm_x4(sbl + off, bl[nb]);
            }
#pragma unroll
            for (int mf = 0; mf < 2; mf++)
#pragma unroll
                for (int nf = 0; nf < 4; nf++) {
                    const uint32_t* bhp = &bh[nf >> 1][(nf & 1) * 2];
                    const uint32_t* blp = &bl[nf >> 1][(nf & 1) * 2];
                    mma_bf16(acc[mf][nf], ah[mf], bhp);
                    mma_bf16(acc[mf][nf], ah[mf], blp);
                    mma_bf16(acc[mf][nf], al[mf], bhp);
                }
        }

        CP_WAIT1();    // next stage's data landed
        __syncthreads();
        cur = cur + 1; if (cur >= NSTAGE) cur -= NSTAGE;
    }
}

// ============================ GEMM kernels ===================================
__global__ __launch_bounds__(NTHR, 1) void k_gemm_scores(const unsigned char* __restrict__ cmask) {
    extern __shared__ char sm[];
    const int b = blockIdx.z, i0 = blockIdx.y * 128, j0 = blockIdx.x * 128;
    const size_t aBase = ((size_t)b * LSEQ + i0) * DIM;
    const size_t bBase = ((size_t)b * LSEQ + j0) * DIM;
    float acc[2][4][4];
    gemm_tile(g_c2_hi + aBase, g_c2_lo + aBase, DIM,
              g_c1_hi + bBase, g_c1_lo + bBase, DIM, DIM / KC, sm, acc);

    const int w = threadIdx.x >> 5, lane = threadIdx.x & 31;
    const int wm = (w & 3) * 32, wn = (w >> 2) * 32;
#pragma unroll
    for (int mf = 0; mf < 2; mf++)
#pragma unroll
        for (int nf = 0; nf < 4; nf++) {
            const int gj = j0 + wn + nf * 8 + (lane & 3) * 2;
            const unsigned char m0 = cmask[b * LSEQ + gj];
            const unsigned char m1 = cmask[b * LSEQ + gj + 1];
#pragma unroll
            for (int half = 0; half < 2; half++) {
                const int gi = i0 + wm + mf * 16 + (lane >> 2) + half * 8;
                float2 v = make_float2(acc[mf][nf][2 * half], acc[mf][nf][2 * half + 1]);
                if (gi == gj || m0) v.x = -INFINITY;
                if (gi == gj + 1 || m1) v.y = -INFINITY;
                *(float2*)&g_scores[((size_t)(b * LSEQ) + gi) * LSEQ + gj] = v;
            }
        }
}

__global__ __launch_bounds__(NTHR, 1) void k_gemm_aug() {
    extern __shared__ char sm[];
    const int b = blockIdx.z, i0 = blockIdx.y * 128, n0 = blockIdx.x * 128;
    const size_t aBase = ((size_t)b * LSEQ + i0) * LSEQ;
    const size_t bBase = ((size_t)b * DIM + n0) * LSEQ;
    float acc[2][4][4];
    gemm_tile(g_alpha_hi + aBase, g_alpha_lo + aBase, LSEQ,
              g_c1t_hi + bBase, g_c1t_lo + bBase, LSEQ, LSEQ / KC, sm, acc);

    const int w = threadIdx.x >> 5, lane = threadIdx.x & 31;
    const int wm = (w & 3) * 32, wn = (w >> 2) * 32;
#pragma unroll
    for (int mf = 0; mf < 2; mf++)
#pragma unroll
        for (int nf = 0; nf < 4; nf++) {
            const int gn = n0 + wn + nf * 8 + (lane & 3) * 2;
#pragma unroll
            for (int half = 0; half < 2; half++) {
                const int gi = i0 + wm + mf * 16 + (lane >> 2) + half * 8;
                float2 v = make_float2(acc[mf][nf][2 * half], acc[mf][nf][2 * half + 1]);
                *(float2*)&g_aug[((size_t)(b * LSEQ) + gi) * DIM + gn] = v;
            }
        }
}

__global__ __launch_bounds__(NTHR, 1) void k_gemm_fusion(const float* __restrict__ c2,
                                                         const float* __restrict__ bf,
                                                         float* __restrict__ out) {
    extern __shared__ char sm[];
    const int n0 = blockIdx.x * 128, m0 = blockIdx.y * 128;
    const size_t aBase = (size_t)m0 * (4 * DIM);
    const size_t bBase = (size_t)n0 * (4 * DIM);
    float acc[2][4][4];
    gemm_tile(g_z_hi + aBase, g_z_lo + aBase, 4 * DIM,
              g_wft_hi + bBase, g_wft_lo + bBase, 4 * DIM, (4 * DIM) / KC, sm, acc);

    const int w = threadIdx.x >> 5, lane = threadIdx.x & 31;
    const int wm = (w & 3) * 32, wn = (w >> 2) * 32;
#pragma unroll
    for (int mf = 0; mf < 2; mf++)
#pragma unroll
        for (int nf = 0; nf < 4; nf++) {
            const int col = n0 + wn + nf * 8 + (lane & 3) * 2;
            const float bf0 = bf[col], bf1 = bf[col + 1];
#pragma unroll
            for (int half = 0; half < 2; half++) {
                const int grow = m0 + wm + mf * 16 + (lane >> 2) + half * 8;
                const float g = g_gate[grow];
                const float2 cv = *(const float2*)&c2[(size_t)grow * DIM + col];
                float2 v;
                v.x = g * tanhf(acc[mf][nf][2 * half] + bf0) + (1.f - g) * cv.x;
                v.y = g * tanhf(acc[mf][nf][2 * half + 1] + bf1) + (1.f - g) * cv.y;
                *(float2*)&out[(size_t)grow * DIM + col] = v;
            }
        }
}

// ============================ softmax + alpha split ==========================
__global__ __launch_bounds__(256) void k_softmax() {
    const size_t row = blockIdx.x;
    const float4* p4 = (const float4*)(g_scores + row * LSEQ);
    const int t = threadIdx.x;
    const int lane = t & 31, wrp = t >> 5;

    float4 va = p4[2 * t];
    float4 vb = p4[2 * t + 1];

    float m = fmaxf(fmaxf(fmaxf(va.x, va.y), fmaxf(va.z, va.w)),
                    fmaxf(fmaxf(vb.x, vb.y), fmaxf(vb.z, vb.w)));
#pragma unroll
    for (int s = 16; s > 0; s >>= 1)
        m = fmaxf(m, __shfl_xor_sync(0xffffffffu, m, s));
    __shared__ float red[8];
    if (lane == 0) red[wrp] = m;
    __syncthreads();
    if (wrp == 0) {
        float x = red[lane & 7];
#pragma unroll
        for (int s = 4; s > 0; s >>= 1)
            x = fmaxf(x, __shfl_xor_sync(0xffffffffu, x, s));
        if (lane == 0) red[0] = x;
    }
    __syncthreads();
    m = red[0];

    va.x = __expf(va.x - m); va.y = __expf(va.y - m);
    va.z = __expf(va.z - m); va.w = __expf(va.w - m);
    vb.x = __expf(vb.x - m); vb.y = __expf(vb.y - m);
    vb.z = __expf(vb.z - m); vb.w = __expf(vb.w - m);
    float sum = (va.x + va.y + va.z + va.w) + (vb.x + vb.y + vb.z + vb.w);
#pragma unroll
    for (int s = 16; s > 0; s >>= 1)
        sum += __shfl_xor_sync(0xffffffffu, sum, s);
    __shared__ float red2[8];
    if (lane == 0) red2[wrp] = sum;
    __syncthreads();
    if (wrp == 0) {
        float x = red2[lane & 7];
#pragma unroll
        for (int s = 4; s > 0; s >>= 1)
            x += __shfl_xor_sync(0xffffffffu, x, s);
        if (lane == 0) red2[0] = x;
    }
    __syncthreads();
    const float inv = 1.f / red2[0];

    const size_t o = row * LSEQ + (size_t)t * 8;
    float vals[8] = {va.x * inv, va.y * inv, va.z * inv, va.w * inv,
                     vb.x * inv, vb.y * inv, vb.z * inv, vb.w * inv};
#pragma unroll
    for (int p = 0; p < 4; p++) {
        const float a0 = vals[2 * p], a1 = vals[2 * p + 1];
        const __nv_bfloat16 h0 = __float2bfloat16(a0);
        const __nv_bfloat16 h1 = __float2bfloat16(a1);
        __nv_bfloat162 hh; hh.x = h0; hh.y = h1;
        __nv_bfloat162 ll;
        ll.x = __float2bfloat16(a0 - __bfloat162float(h0));
        ll.y = __float2bfloat16(a1 - __bfloat162float(h1));
        *(__nv_bfloat162*)&g_alpha_hi[o + 2 * p] = hh;
        *(__nv_bfloat162*)&g_alpha_lo[o + 2 * p] = ll;
    }
}

// ============================ z prep + gate ==================================
__global__ __launch_bounds__(256) void k_prep_z(const float* __restrict__ c2,
                                                const float* __restrict__ Wg,
                                                const float* __restrict__ bg) {
    const int m = blockIdx.x;
    const int t = threadIdx.x;
    const float c2v = c2[(size_t)m * DIM + t];
    const float av  = g_aug[(size_t)m * DIM + t];
    const float z[4] = {c2v, av, c2v * av, c2v - av};
    float part = 0.f;
#pragma unroll
    for (int s = 0; s < 4; s++) {
        const size_t o = (size_t)m * (4 * DIM) + s * DIM + t;
        const __nv_bfloat16 h = __float2bfloat16(z[s]);
        g_z_hi[o] = h;
        g_z_lo[o] = __float2bfloat16(z[s] - __bfloat162float(h));
        part += z[s] * Wg[s * DIM + t];
    }
    __shared__ float red[256];
    red[t] = part;
    __syncthreads();
    for (int s = 128; s > 0; s >>= 1) {
        if (t < s) red[t] += red[t + s];
        __syncthreads();
    }
    if (t == 0) g_gate[m] = 1.f / (1.f + __expf(-(red[0] + bg[0])));
}

// ============================ launch =========================================
extern "C" void kernel_launch(void* const* d_in, const int* in_sizes, int n_in,
                              void* d_out, int out_size) {
    const float* c1 = (const float*)d_in[0];
    const float* c2 = (const float*)d_in[1];
    const unsigned char* cmask = (const unsigned char*)d_in[2];
    const float* Wf = (const float*)d_in[3];
    const float* bf = (const float*)d_in[4];
    const float* Wg = (const float*)d_in[5];
    const float* bg = (const float*)d_in[6];
    float* out = (float*)d_out;

    cudaFuncSetAttribute(k_gemm_scores, cudaFuncAttributeMaxDynamicSharedMemorySize, SMEM_DYN);
    cudaFuncSetAttribute(k_gemm_aug,    cudaFuncAttributeMaxDynamicSharedMemorySize, SMEM_DYN);
    cudaFuncSetAttribute(k_gemm_fusion, cudaFuncAttributeMaxDynamicSharedMemorySize, SMEM_DYN);

    k_prep_split<<<(BATCH * LSEQ * DIM) / 256, 256>>>(c1, c2);
    k_prep_t<<<dim3(LSEQ / 32, DIM / 32, BATCH), dim3(32, 8)>>>(c1);
    k_prep_wft<<<(DIM * 4 * DIM) / 256, 256>>>(Wf);

    k_gemm_scores<<<dim3(LSEQ / 128, LSEQ / 128, BATCH), NTHR, SMEM_DYN>>>(cmask);
    k_softmax<<<BATCH * LSEQ, 256>>>();
    k_gemm_aug<<<dim3(DIM / 128, LSEQ / 128, BATCH), NTHR, SMEM_DYN>>>();
    k_prep_z<<<BATCH * LSEQ, 256>>>(c2, Wg, bg);
    k_gemm_fusion<<<dim3(DIM / 128, (BATCH * LSEQ) / 128), NTHR, SMEM_DYN>>>(c2, bf, out);
}

// round 8
// speedup vs baseline: 1.4611x; 1.4611x over previous
#include <cuda_runtime.h>
#include <cuda_bf16.h>
#include <cstdint>
#include <math.h>

#define LSEQ 2048
#define DIM  256
#define BATCH 8

#define KC 32          // bf16 k per chunk
#define PAD_STR 40     // smem row stride in elements (80B: conflict-free for ldmatrix)
#define TILE_B (128 * PAD_STR * 2)          // 10240 bytes per tile
#define STAGE_B (4 * TILE_B)                // Ah, Al, Bh, Bl
#define NSTAGE 3
#define SMEM_DYN (NSTAGE * STAGE_B)         // 3 stages = 122880 bytes

// ============================ PTX helpers ====================================
__device__ __forceinline__ uint32_t smem_to_u32(const void* p) {
    uint32_t a;
    asm("{ .reg .u64 t; cvta.to.shared.u64 t, %1; cvt.u32.u64 %0, t; }"
        : "=r"(a) : "l"(p));
    return a;
}
__device__ __forceinline__ void cp_async16(uint32_t dst, const void* src) {
    asm volatile("cp.async.cg.shared.global [%0], [%1], 16;" :: "r"(dst), "l"(src));
}
#define CP_COMMIT() asm volatile("cp.async.commit_group;" ::: "memory")
#define CP_WAIT1()  asm volatile("cp.async.wait_group 1;" ::: "memory")

__device__ __forceinline__ void ldsm_x4(uint32_t addr, uint32_t* r) {
    asm volatile("ldmatrix.sync.aligned.m8n8.x4.shared.b16 {%0,%1,%2,%3}, [%4];"
                 : "=r"(r[0]), "=r"(r[1]), "=r"(r[2]), "=r"(r[3]) : "r"(addr));
}
// NOTE: non-volatile — outputs are registers with tracked data deps, so ptxas
// may interleave independent accumulator chains across these asm blocks.
__device__ __forceinline__ void mma_bf16(float* c, const uint32_t* a, const uint32_t* b) {
    asm("mma.sync.aligned.m16n8k16.row.col.f32.bf16.bf16.f32 "
        "{%0,%1,%2,%3}, {%4,%5,%6,%7}, {%8,%9}, {%0,%1,%2,%3};"
        : "+f"(c[0]), "+f"(c[1]), "+f"(c[2]), "+f"(c[3])
        : "r"(a[0]), "r"(a[1]), "r"(a[2]), "r"(a[3]), "r"(b[0]), "r"(b[1]));
}

// ============================ device scratch =================================
static __device__ __nv_bfloat16 g_c1_hi[(size_t)BATCH * LSEQ * DIM];
static __device__ __nv_bfloat16 g_c1_lo[(size_t)BATCH * LSEQ * DIM];
static __device__ __nv_bfloat16 g_c2_hi[(size_t)BATCH * LSEQ * DIM];
static __device__ __nv_bfloat16 g_c2_lo[(size_t)BATCH * LSEQ * DIM];
static __device__ __nv_bfloat16 g_c1t_hi[(size_t)BATCH * DIM * LSEQ];
static __device__ __nv_bfloat16 g_c1t_lo[(size_t)BATCH * DIM * LSEQ];
static __device__ __nv_bfloat16 g_wft_hi[(size_t)DIM * 4 * DIM];   // [n=256][k=1024]
static __device__ __nv_bfloat16 g_wft_lo[(size_t)DIM * 4 * DIM];
static __device__ float         g_scores[(size_t)BATCH * LSEQ * LSEQ];
static __device__ __nv_bfloat16 g_alpha_hi[(size_t)BATCH * LSEQ * LSEQ];
static __device__ __nv_bfloat16 g_alpha_lo[(size_t)BATCH * LSEQ * LSEQ];
static __device__ float         g_aug[(size_t)BATCH * LSEQ * DIM];
static __device__ __nv_bfloat16 g_z_hi[(size_t)BATCH * LSEQ * 4 * DIM];
static __device__ __nv_bfloat16 g_z_lo[(size_t)BATCH * LSEQ * 4 * DIM];
static __device__ float         g_gate[BATCH * LSEQ];

// ============================ prep kernels ===================================
__global__ __launch_bounds__(256) void k_prep_split(const float* __restrict__ c1,
                                                    const float* __restrict__ c2) {
    size_t i = (size_t)blockIdx.x * 256 + threadIdx.x;
    if (i < (size_t)BATCH * LSEQ * DIM) {
        float v = c1[i];
        __nv_bfloat16 h = __float2bfloat16(v);
        g_c1_hi[i] = h;
        g_c1_lo[i] = __float2bfloat16(v - __bfloat162float(h));
        v = c2[i];
        h = __float2bfloat16(v);
        g_c2_hi[i] = h;
        g_c2_lo[i] = __float2bfloat16(v - __bfloat162float(h));
    }
}

__global__ __launch_bounds__(256) void k_prep_t(const float* __restrict__ c1) {
    __shared__ float tile[32][33];
    const int b = blockIdx.z;
    const int j0 = blockIdx.x * 32, d0 = blockIdx.y * 32;
    const float* src = c1 + (size_t)b * LSEQ * DIM;
    const int tx = threadIdx.x, ty = threadIdx.y;  // block (32, 8)
#pragma unroll
    for (int r = 0; r < 32; r += 8)
        tile[ty + r][tx] = src[(size_t)(j0 + ty + r) * DIM + d0 + tx];
    __syncthreads();
#pragma unroll
    for (int r = 0; r < 32; r += 8) {
        float v = tile[tx][ty + r];
        __nv_bfloat16 h = __float2bfloat16(v);
        size_t o = (size_t)b * DIM * LSEQ + (size_t)(d0 + ty + r) * LSEQ + j0 + tx;
        g_c1t_hi[o] = h;
        g_c1t_lo[o] = __float2bfloat16(v - __bfloat162float(h));
    }
}

__global__ __launch_bounds__(256) void k_prep_wft(const float* __restrict__ Wf) {
    int i = blockIdx.x * 256 + threadIdx.x;  // i = n*1024 + k
    if (i < DIM * 4 * DIM) {
        int n = i >> 10, k = i & 1023;
        float v = Wf[(size_t)k * DIM + n];
        __nv_bfloat16 h = __float2bfloat16(v);
        g_wft_hi[i] = h;
        g_wft_lo[i] = __float2bfloat16(v - __bfloat162float(h));
    }
}

// ============================ GEMM mainloop ==================================
// Block tile 128x128, 8 warps, warp tile 64x32 (warp grid 2m x 4n).
// A: [m][k] row-major hi/lo; B: [n][k] row-major hi/lo (i.e. B^T).
// 3 passes: Ah*Bh + Ah*Bl + Al*Bh accumulated into fp32, pass-major ordering
// so consecutive MMAs hit independent accumulators (16-deep ILP).
__device__ __forceinline__ void load_chunk(uint32_t sbase,
                                           const __nv_bfloat16* __restrict__ Ah,
                                           const __nv_bfloat16* __restrict__ Al,
                                           size_t aStr,
                                           const __nv_bfloat16* __restrict__ Bh,
                                           const __nv_bfloat16* __restrict__ Bl,
                                           size_t bStr, int kOff) {
    const int t = threadIdx.x;
    const int c = (t & 3) * 8;   // bf16 col within 32
    const int r = t >> 2;        // 0..63
    const uint32_t soff = (uint32_t)(r * PAD_STR + c) * 2;
    const uint32_t soff2 = soff + 64 * PAD_STR * 2;
    {
        const __nv_bfloat16* g = Ah + (size_t)r * aStr + kOff + c;
        cp_async16(sbase + 0 * TILE_B + soff, g);
        cp_async16(sbase + 0 * TILE_B + soff2, g + 64 * aStr);
    }
    {
        const __nv_bfloat16* g = Al + (size_t)r * aStr + kOff + c;
        cp_async16(sbase + 1 * TILE_B + soff, g);
        cp_async16(sbase + 1 * TILE_B + soff2, g + 64 * aStr);
    }
    {
        const __nv_bfloat16* g = Bh + (size_t)r * bStr + kOff + c;
        cp_async16(sbase + 2 * TILE_B + soff, g);
        cp_async16(sbase + 2 * TILE_B + soff2, g + 64 * bStr);
    }
    {
        const __nv_bfloat16* g = Bl + (size_t)r * bStr + kOff + c;
        cp_async16(sbase + 3 * TILE_B + soff, g);
        cp_async16(sbase + 3 * TILE_B + soff2, g + 64 * bStr);
    }
}

__device__ __forceinline__ void gemm_tile(const __nv_bfloat16* __restrict__ Ah,
                                          const __nv_bfloat16* __restrict__ Al,
                                          size_t aStr,
                                          const __nv_bfloat16* __restrict__ Bh,
                                          const __nv_bfloat16* __restrict__ Bl,
                                          size_t bStr, int nChunks, char* sm,
                                          float acc[4][4][4]) {
    const int t = threadIdx.x;
    const int w = t >> 5, lane = t & 31;
    const int wm = (w & 1) * 64;        // warp m offset
    const int wn = (w >> 1) * 32;       // warp n offset
    const uint32_t smb = smem_to_u32(sm);

#pragma unroll
    for (int mf = 0; mf < 4; mf++)
#pragma unroll
        for (int nf = 0; nf < 4; nf++)
#pragma unroll
            for (int e = 0; e < 4; e++) acc[mf][nf][e] = 0.f;

    // per-lane ldmatrix base offsets
    const int arow = wm + (lane & 15);
    const int acol = (lane >> 4) * 8;
    const int brow = wn + (lane & 7) + ((lane >> 4) ? 8 : 0);
    const int bcol = ((lane >> 3) & 1) * 8;

    // prologue: stages 0 and 1 (nChunks >= 2 always here)
    load_chunk(smb + 0 * STAGE_B, Ah, Al, aStr, Bh, Bl, bStr, 0);
    CP_COMMIT();
    load_chunk(smb + 1 * STAGE_B, Ah, Al, aStr, Bh, Bl, bStr, KC);
    CP_COMMIT();
    CP_WAIT1();        // stage 0 ready
    __syncthreads();

    int cur = 0;
    for (int kc = 0; kc < nChunks; kc++) {
        if (kc + 2 < nChunks) {
            int nxt = cur + 2; if (nxt >= NSTAGE) nxt -= NSTAGE;
            load_chunk(smb + (uint32_t)nxt * STAGE_B, Ah, Al, aStr, Bh, Bl, bStr,
                       (kc + 2) * KC);
        }
        CP_COMMIT();   // empty group on tail iterations keeps wait counts uniform

        const uint32_t s = (uint32_t)cur * STAGE_B;
        const uint32_t sah = smb + s + 0 * TILE_B;
        const uint32_t sal = smb + s + 1 * TILE_B;
        const uint32_t sbh = smb + s + 2 * TILE_B;
        const uint32_t sbl = smb + s + 3 * TILE_B;

#pragma unroll
        for (int ks = 0; ks < 2; ks++) {
            const int k0 = ks * 16;
            uint32_t ah[4][4], al[4][4], bh[2][4], bl[2][4];
#pragma unroll
            for (int mf = 0; mf < 4; mf++) {
                const uint32_t off = (uint32_t)((arow + mf * 16) * PAD_STR + acol + k0) * 2;
                ldsm_x4(sah + off, ah[mf]);
                ldsm_x4(sal + off, al[mf]);
            }
#pragma unroll
            for (int nb = 0; nb < 2; nb++) {
                const uint32_t off = (uint32_t)((brow + nb * 16) * PAD_STR + bcol + k0) * 2;
                ldsm_x4(sbh + off, bh[nb]);
                ldsm_x4(sbl + off, bl[nb]);
            }
            // pass-major: consecutive MMAs hit 16 different accumulators, so
            // same-acc reuse distance is 16 MMA issues (no RAW back-to-back).
#pragma unroll
            for (int p = 0; p < 3; p++)
#pragma unroll
                for (int mf = 0; mf < 4; mf++)
#pragma unroll
                    for (int nf = 0; nf < 4; nf++) {
                        const uint32_t* aa = (p == 2) ? al[mf] : ah[mf];
                        const uint32_t* bb = (p == 1) ? &bl[nf >> 1][(nf & 1) * 2]
                                                      : &bh[nf >> 1][(nf & 1) * 2];
                        mma_bf16(acc[mf][nf], aa, bb);
                    }
        }

        CP_WAIT1();    // next stage's data landed
        __syncthreads();
        cur = cur + 1; if (cur >= NSTAGE) cur -= NSTAGE;
    }
}

// ============================ GEMM kernels ===================================
__global__ __launch_bounds__(256, 1) void k_gemm_scores(const unsigned char* __restrict__ cmask) {
    extern __shared__ char sm[];
    const int b = blockIdx.z, i0 = blockIdx.y * 128, j0 = blockIdx.x * 128;
    const size_t aBase = ((size_t)b * LSEQ + i0) * DIM;
    const size_t bBase = ((size_t)b * LSEQ + j0) * DIM;
    float acc[4][4][4];
    gemm_tile(g_c2_hi + aBase, g_c2_lo + aBase, DIM,
              g_c1_hi + bBase, g_c1_lo + bBase, DIM, DIM / KC, sm, acc);

    const int w = threadIdx.x >> 5, lane = threadIdx.x & 31;
    const int wm = (w & 1) * 64, wn = (w >> 1) * 32;
#pragma unroll
    for (int mf = 0; mf < 4; mf++)
#pragma unroll
        for (int nf = 0; nf < 4; nf++) {
            const int gj = j0 + wn + nf * 8 + (lane & 3) * 2;
            const unsigned char m0 = cmask[b * LSEQ + gj];
            const unsigned char m1 = cmask[b * LSEQ + gj + 1];
#pragma unroll
            for (int half = 0; half < 2; half++) {
                const int gi = i0 + wm + mf * 16 + (lane >> 2) + half * 8;
                float2 v = make_float2(acc[mf][nf][2 * half], acc[mf][nf][2 * half + 1]);
                if (gi == gj || m0) v.x = -INFINITY;
                if (gi == gj + 1 || m1) v.y = -INFINITY;
                *(float2*)&g_scores[((size_t)(b * LSEQ) + gi) * LSEQ + gj] = v;
            }
        }
}

__global__ __launch_bounds__(256, 1) void k_gemm_aug() {
    extern __shared__ char sm[];
    const int b = blockIdx.z, i0 = blockIdx.y * 128, n0 = blockIdx.x * 128;
    const size_t aBase = ((size_t)b * LSEQ + i0) * LSEQ;
    const size_t bBase = ((size_t)b * DIM + n0) * LSEQ;
    float acc[4][4][4];
    gemm_tile(g_alpha_hi + aBase, g_alpha_lo + aBase, LSEQ,
              g_c1t_hi + bBase, g_c1t_lo + bBase, LSEQ, LSEQ / KC, sm, acc);

    const int w = threadIdx.x >> 5, lane = threadIdx.x & 31;
    const int wm = (w & 1) * 64, wn = (w >> 1) * 32;
#pragma unroll
    for (int mf = 0; mf < 4; mf++)
#pragma unroll
        for (int nf = 0; nf < 4; nf++) {
            const int gn = n0 + wn + nf * 8 + (lane & 3) * 2;
#pragma unroll
            for (int half = 0; half < 2; half++) {
                const int gi = i0 + wm + mf * 16 + (lane >> 2) + half * 8;
                float2 v = make_float2(acc[mf][nf][2 * half], acc[mf][nf][2 * half + 1]);
                *(float2*)&g_aug[((size_t)(b * LSEQ) + gi) * DIM + gn] = v;
            }
        }
}

__global__ __launch_bounds__(256, 1) void k_gemm_fusion(const float* __restrict__ c2,
                                                        const float* __restrict__ bf,
                                                        float* __restrict__ out) {
    extern __shared__ char sm[];
    const int n0 = blockIdx.x * 128, m0 = blockIdx.y * 128;
    const size_t aBase = (size_t)m0 * (4 * DIM);
    const size_t bBase = (size_t)n0 * (4 * DIM);
    float acc[4][4][4];
    gemm_tile(g_z_hi + aBase, g_z_lo + aBase, 4 * DIM,
              g_wft_hi + bBase, g_wft_lo + bBase, 4 * DIM, (4 * DIM) / KC, sm, acc);

    const int w = threadIdx.x >> 5, lane = threadIdx.x & 31;
    const int wm = (w & 1) * 64, wn = (w >> 1) * 32;
#pragma unroll
    for (int mf = 0; mf < 4; mf++)
#pragma unroll
        for (int nf = 0; nf < 4; nf++) {
            const int col = n0 + wn + nf * 8 + (lane & 3) * 2;
            const float bf0 = bf[col], bf1 = bf[col + 1];
#pragma unroll
            for (int half = 0; half < 2; half++) {
                const int grow = m0 + wm + mf * 16 + (lane >> 2) + half * 8;
                const float g = g_gate[grow];
                const float2 cv = *(const float2*)&c2[(size_t)grow * DIM + col];
                float2 v;
                v.x = g * tanhf(acc[mf][nf][2 * half] + bf0) + (1.f - g) * cv.x;
                v.y = g * tanhf(acc[mf][nf][2 * half + 1] + bf1) + (1.f - g) * cv.y;
                *(float2*)&out[(size_t)grow * DIM + col] = v;
            }
        }
}

// ============================ softmax + alpha split ==========================
__global__ __launch_bounds__(256) void k_softmax() {
    const size_t row = blockIdx.x;
    const float4* p4 = (const float4*)(g_scores + row * LSEQ);
    const int t = threadIdx.x;
    const int lane = t & 31, wrp = t >> 5;

    float4 va = p4[2 * t];
    float4 vb = p4[2 * t + 1];

    float m = fmaxf(fmaxf(fmaxf(va.x, va.y), fmaxf(va.z, va.w)),
                    fmaxf(fmaxf(vb.x, vb.y), fmaxf(vb.z, vb.w)));
#pragma unroll
    for (int s = 16; s > 0; s >>= 1)
        m = fmaxf(m, __shfl_xor_sync(0xffffffffu, m, s));
    __shared__ float red[8];
    if (lane == 0) red[wrp] = m;
    __syncthreads();
    if (wrp == 0) {
        float x = red[lane & 7];
#pragma unroll
        for (int s = 4; s > 0; s >>= 1)
            x = fmaxf(x, __shfl_xor_sync(0xffffffffu, x, s));
        if (lane == 0) red[0] = x;
    }
    __syncthreads();
    m = red[0];

    va.x = __expf(va.x - m); va.y = __expf(va.y - m);
    va.z = __expf(va.z - m); va.w = __expf(va.w - m);
    vb.x = __expf(vb.x - m); vb.y = __expf(vb.y - m);
    vb.z = __expf(vb.z - m); vb.w = __expf(vb.w - m);
    float sum = (va.x + va.y + va.z + va.w) + (vb.x + vb.y + vb.z + vb.w);
#pragma unroll
    for (int s = 16; s > 0; s >>= 1)
        sum += __shfl_xor_sync(0xffffffffu, sum, s);
    __shared__ float red2[8];
    if (lane == 0) red2[wrp] = sum;
    __syncthreads();
    if (wrp == 0) {
        float x = red2[lane & 7];
#pragma unroll
        for (int s = 4; s > 0; s >>= 1)
            x += __shfl_xor_sync(0xffffffffu, x, s);
        if (lane == 0) red2[0] = x;
    }
    __syncthreads();
    const float inv = 1.f / red2[0];

    const size_t o = row * LSEQ + (size_t)t * 8;
    float vals[8] = {va.x * inv, va.y * inv, va.z * inv, va.w * inv,
                     vb.x * inv, vb.y * inv, vb.z * inv, vb.w * inv};
#pragma unroll
    for (int p = 0; p < 4; p++) {
        const float a0 = vals[2 * p], a1 = vals[2 * p + 1];
        const __nv_bfloat16 h0 = __float2bfloat16(a0);
        const __nv_bfloat16 h1 = __float2bfloat16(a1);
        __nv_bfloat162 hh; hh.x = h0; hh.y = h1;
        __nv_bfloat162 ll;
        ll.x = __float2bfloat16(a0 - __bfloat162float(h0));
        ll.y = __float2bfloat16(a1 - __bfloat162float(h1));
        *(__nv_bfloat162*)&g_alpha_hi[o + 2 * p] = hh;
        *(__nv_bfloat162*)&g_alpha_lo[o + 2 * p] = ll;
    }
}

// ============================ z prep + gate ==================================
__global__ __launch_bounds__(256) void k_prep_z(const float* __restrict__ c2,
                                                const float* __restrict__ Wg,
                                                const float* __restrict__ bg) {
    const int m = blockIdx.x;
    const int t = threadIdx.x;
    const float c2v = c2[(size_t)m * DIM + t];
    const float av  = g_aug[(size_t)m * DIM + t];
    const float z[4] = {c2v, av, c2v * av, c2v - av};
    float part = 0.f;
#pragma unroll
    for (int s = 0; s < 4; s++) {
        const size_t o = (size_t)m * (4 * DIM) + s * DIM + t;
        const __nv_bfloat16 h = __float2bfloat16(z[s]);
        g_z_hi[o] = h;
        g_z_lo[o] = __float2bfloat16(z[s] - __bfloat162float(h));
        part += z[s] * Wg[s * DIM + t];
    }
    __shared__ float red[256];
    red[t] = part;
    __syncthreads();
    for (int s = 128; s > 0; s >>= 1) {
        if (t < s) red[t] += red[t + s];
        __syncthreads();
    }
    if (t == 0) g_gate[m] = 1.f / (1.f + __expf(-(red[0] + bg[0])));
}

// ============================ launch =========================================
extern "C" void kernel_launch(void* const* d_in, const int* in_sizes, int n_in,
                              void* d_out, int out_size) {
    const float* c1 = (const float*)d_in[0];
    const float* c2 = (const float*)d_in[1];
    const unsigned char* cmask = (const unsigned char*)d_in[2];
    const float* Wf = (const float*)d_in[3];
    const float* bf = (const float*)d_in[4];
    const float* Wg = (const float*)d_in[5];
    const float* bg = (const float*)d_in[6];
    float* out = (float*)d_out;

    cudaFuncSetAttribute(k_gemm_scores, cudaFuncAttributeMaxDynamicSharedMemorySize, SMEM_DYN);
    cudaFuncSetAttribute(k_gemm_aug,    cudaFuncAttributeMaxDynamicSharedMemorySize, SMEM_DYN);
    cudaFuncSetAttribute(k_gemm_fusion, cudaFuncAttributeMaxDynamicSharedMemorySize, SMEM_DYN);

    k_prep_split<<<(BATCH * LSEQ * DIM) / 256, 256>>>(c1, c2);
    k_prep_t<<<dim3(LSEQ / 32, DIM / 32, BATCH), dim3(32, 8)>>>(c1);
    k_prep_wft<<<(DIM * 4 * DIM) / 256, 256>>>(Wf);

    k_gemm_scores<<<dim3(LSEQ / 128, LSEQ / 128, BATCH), 256, SMEM_DYN>>>(cmask);
    k_softmax<<<BATCH * LSEQ, 256>>>();
    k_gemm_aug<<<dim3(DIM / 128, LSEQ / 128, BATCH), 256, SMEM_DYN>>>();
    k_prep_z<<<BATCH * LSEQ, 256>>>(c2, Wg, bg);
    k_gemm_fusion<<<dim3(DIM / 128, (BATCH * LSEQ) / 128), 256, SMEM_DYN>>>(c2, bf, out);
}

// round 10
// speedup vs baseline: 1.5277x; 1.0456x over previous
#include <cuda_runtime.h>
#include <cuda_bf16.h>
#include <cstdint>
#include <math.h>

#define LSEQ 2048
#define DIM  256
#define BATCH 8

#define KC 32
#define PAD_STR 40
#define TILE_B (128 * PAD_STR * 2)
#define STAGE_B (4 * TILE_B)
#define NSTAGE 3
#define SMEM_DYN (NSTAGE * STAGE_B)

// ============================ PTX helpers ====================================
__device__ __forceinline__ uint32_t smem_to_u32(const void* p) {
    uint32_t a;
    asm("{ .reg .u64 t; cvta.to.shared.u64 t, %1; cvt.u32.u64 %0, t; }"
        : "=r"(a) : "l"(p));
    return a;
}
__device__ __forceinline__ void cp_async16(uint32_t dst, const void* src) {
    asm volatile("cp.async.cg.shared.global [%0], [%1], 16;" :: "r"(dst), "l"(src));
}
#define CP_COMMIT() asm volatile("cp.async.commit_group;" ::: "memory")
#define CP_WAIT1()  asm volatile("cp.async.wait_group 1;" ::: "memory")

__device__ __forceinline__ void ldsm_x4(uint32_t addr, uint32_t* r) {
    asm volatile("ldmatrix.sync.aligned.m8n8.x4.shared.b16 {%0,%1,%2,%3}, [%4];"
                 : "=r"(r[0]), "=r"(r[1]), "=r"(r[2]), "=r"(r[3]) : "r"(addr));
}
__device__ __forceinline__ void mma_bf16(float* c, const uint32_t* a, const uint32_t* b) {
    asm("mma.sync.aligned.m16n8k16.row.col.f32.bf16.bf16.f32 "
        "{%0,%1,%2,%3}, {%4,%5,%6,%7}, {%8,%9}, {%0,%1,%2,%3};"
        : "+f"(c[0]), "+f"(c[1]), "+f"(c[2]), "+f"(c[3])
        : "r"(a[0]), "r"(a[1]), "r"(a[2]), "r"(a[3]), "r"(b[0]), "r"(b[1]));
}

// ============================ device scratch =================================
static __device__ __nv_bfloat16 g_c1_hi[(size_t)BATCH * LSEQ * DIM];
static __device__ __nv_bfloat16 g_c1_lo[(size_t)BATCH * LSEQ * DIM];
static __device__ __nv_bfloat16 g_c2_hi[(size_t)BATCH * LSEQ * DIM];
static __device__ __nv_bfloat16 g_c2_lo[(size_t)BATCH * LSEQ * DIM];
static __device__ __nv_bfloat16 g_c1t_hi[(size_t)BATCH * DIM * LSEQ];
static __device__ __nv_bfloat16 g_c1t_lo[(size_t)BATCH * DIM * LSEQ];
static __device__ __nv_bfloat16 g_wft_hi[(size_t)DIM * 4 * DIM];   // [n=256][k=1024]
static __device__ float         g_scores[(size_t)BATCH * LSEQ * LSEQ];
static __device__ __nv_bfloat16 g_alpha_hi[(size_t)BATCH * LSEQ * LSEQ];
static __device__ __nv_bfloat16 g_alpha_lo[(size_t)BATCH * LSEQ * LSEQ];
static __device__ float         g_aug[(size_t)BATCH * LSEQ * DIM];
static __device__ __nv_bfloat16 g_z_hi[(size_t)BATCH * LSEQ * 4 * DIM];
static __device__ __nv_bfloat16 g_z_lo[(size_t)BATCH * LSEQ * 4 * DIM];
static __device__ float         g_gate[BATCH * LSEQ];

// ============================ prep kernels ===================================
__global__ __launch_bounds__(256) void k_prep_split(const float* __restrict__ c1,
                                                    const float* __restrict__ c2) {
    size_t i = (size_t)blockIdx.x * 256 + threadIdx.x;
    if (i < (size_t)BATCH * LSEQ * DIM) {
        float v = c1[i];
        __nv_bfloat16 h = __float2bfloat16(v);
        g_c1_hi[i] = h;
        g_c1_lo[i] = __float2bfloat16(v - __bfloat162float(h));
        v = c2[i];
        h = __float2bfloat16(v);
        g_c2_hi[i] = h;
        g_c2_lo[i] = __float2bfloat16(v - __bfloat162float(h));
    }
}

__global__ __launch_bounds__(256) void k_prep_t(const float* __restrict__ c1) {
    __shared__ float tile[32][33];
    const int b = blockIdx.z;
    const int j0 = blockIdx.x * 32, d0 = blockIdx.y * 32;
    const float* src = c1 + (size_t)b * LSEQ * DIM;
    const int tx = threadIdx.x, ty = threadIdx.y;  // block (32, 8)
#pragma unroll
    for (int r = 0; r < 32; r += 8)
        tile[ty + r][tx] = src[(size_t)(j0 + ty + r) * DIM + d0 + tx];
    __syncthreads();
#pragma unroll
    for (int r = 0; r < 32; r += 8) {
        float v = tile[tx][ty + r];
        __nv_bfloat16 h = __float2bfloat16(v);
        size_t o = (size_t)b * DIM * LSEQ + (size_t)(d0 + ty + r) * LSEQ + j0 + tx;
        g_c1t_hi[o] = h;
        g_c1t_lo[o] = __float2bfloat16(v - __bfloat162float(h));
    }
}

__global__ __launch_bounds__(256) void k_prep_wft(const float* __restrict__ Wf) {
    int i = blockIdx.x * 256 + threadIdx.x;  // i = n*1024 + k
    if (i < DIM * 4 * DIM) {
        int n = i >> 10, k = i & 1023;
        g_wft_hi[i] = __float2bfloat16(Wf[(size_t)k * DIM + n]);
    }
}

// ============================ HMMA GEMM mainloop =============================
// Block tile 128x128, 8 warps, warp tile 64x32.
// TWO_PASS=false: 3 passes Ah*Bh + Ah*Bl + Al*Bh (pair x pair).
// TWO_PASS=true : 2 passes Ah*Bh + Al*Bh (pair x single); Bl never loaded.
template <bool TWO_PASS>
__device__ __forceinline__ void load_chunk(uint32_t sbase,
                                           const __nv_bfloat16* __restrict__ Ah,
                                           const __nv_bfloat16* __restrict__ Al,
                                           size_t aStr,
                                           const __nv_bfloat16* __restrict__ Bh,
                                           const __nv_bfloat16* __restrict__ Bl,
                                           size_t bStr, int kOff) {
    const int t = threadIdx.x;
    const int c = (t & 3) * 8;
    const int r = t >> 2;
    const uint32_t soff = (uint32_t)(r * PAD_STR + c) * 2;
    const uint32_t soff2 = soff + 64 * PAD_STR * 2;
    {
        const __nv_bfloat16* g = Ah + (size_t)r * aStr + kOff + c;
        cp_async16(sbase + 0 * TILE_B + soff, g);
        cp_async16(sbase + 0 * TILE_B + soff2, g + 64 * aStr);
    }
    {
        const __nv_bfloat16* g = Al + (size_t)r * aStr + kOff + c;
        cp_async16(sbase + 1 * TILE_B + soff, g);
        cp_async16(sbase + 1 * TILE_B + soff2, g + 64 * aStr);
    }
    {
        const __nv_bfloat16* g = Bh + (size_t)r * bStr + kOff + c;
        cp_async16(sbase + 2 * TILE_B + soff, g);
        cp_async16(sbase + 2 * TILE_B + soff2, g + 64 * bStr);
    }
    if (!TWO_PASS) {
        const __nv_bfloat16* g = Bl + (size_t)r * bStr + kOff + c;
        cp_async16(sbase + 3 * TILE_B + soff, g);
        cp_async16(sbase + 3 * TILE_B + soff2, g + 64 * bStr);
    }
}

template <bool TWO_PASS>
__device__ __forceinline__ void gemm_tile(const __nv_bfloat16* __restrict__ Ah,
                                          const __nv_bfloat16* __restrict__ Al,
                                          size_t aStr,
                                          const __nv_bfloat16* __restrict__ Bh,
                                          const __nv_bfloat16* __restrict__ Bl,
                                          size_t bStr, int nChunks, char* sm,
                                          float acc[4][4][4]) {
    const int t = threadIdx.x;
    const int w = t >> 5, lane = t & 31;
    const int wm = (w & 1) * 64;
    const int wn = (w >> 1) * 32;
    const uint32_t smb = smem_to_u32(sm);

#pragma unroll
    for (int mf = 0; mf < 4; mf++)
#pragma unroll
        for (int nf = 0; nf < 4; nf++)
#pragma unroll
            for (int e = 0; e < 4; e++) acc[mf][nf][e] = 0.f;

    const int arow = wm + (lane & 15);
    const int acol = (lane >> 4) * 8;
    const int brow = wn + (lane & 7) + ((lane >> 4) ? 8 : 0);
    const int bcol = ((lane >> 3) & 1) * 8;

    load_chunk<TWO_PASS>(smb + 0 * STAGE_B, Ah, Al, aStr, Bh, Bl, bStr, 0);
    CP_COMMIT();
    load_chunk<TWO_PASS>(smb + 1 * STAGE_B, Ah, Al, aStr, Bh, Bl, bStr, KC);
    CP_COMMIT();
    CP_WAIT1();
    __syncthreads();

    int cur = 0;
    for (int kc = 0; kc < nChunks; kc++) {
        if (kc + 2 < nChunks) {
            int nxt = cur + 2; if (nxt >= NSTAGE) nxt -= NSTAGE;
            load_chunk<TWO_PASS>(smb + (uint32_t)nxt * STAGE_B, Ah, Al, aStr, Bh, Bl, bStr,
                                 (kc + 2) * KC);
        }
        CP_COMMIT();

        const uint32_t s = (uint32_t)cur * STAGE_B;
        const uint32_t sah = smb + s + 0 * TILE_B;
        const uint32_t sal = smb + s + 1 * TILE_B;
        const uint32_t sbh = smb + s + 2 * TILE_B;
        const uint32_t sbl = smb + s + 3 * TILE_B;

#pragma unroll
        for (int ks = 0; ks < 2; ks++) {
            const int k0 = ks * 16;
            uint32_t ah[4][4], al[4][4], bh[2][4], bl[2][4];
#pragma unroll
            for (int mf = 0; mf < 4; mf++) {
                const uint32_t off = (uint32_t)((arow + mf * 16) * PAD_STR + acol + k0) * 2;
                ldsm_x4(sah + off, ah[mf]);
                ldsm_x4(sal + off, al[mf]);
            }
#pragma unroll
            for (int nb = 0; nb < 2; nb++) {
                const uint32_t off = (uint32_t)((brow + nb * 16) * PAD_STR + bcol + k0) * 2;
                ldsm_x4(sbh + off, bh[nb]);
                if (!TWO_PASS) ldsm_x4(sbl + off, bl[nb]);
            }
            const int NP = TWO_PASS ? 2 : 3;
#pragma unroll
            for (int p = 0; p < NP; p++)
#pragma unroll
                for (int mf = 0; mf < 4; mf++)
#pragma unroll
                    for (int nf = 0; nf < 4; nf++) {
                        const uint32_t* aa;
                        const uint32_t* bb;
                        if (TWO_PASS) {
                            aa = (p == 1) ? al[mf] : ah[mf];
                            bb = &bh[nf >> 1][(nf & 1) * 2];
                        } else {
                            aa = (p == 2) ? al[mf] : ah[mf];
                            bb = (p == 1) ? &bl[nf >> 1][(nf & 1) * 2]
                                          : &bh[nf >> 1][(nf & 1) * 2];
                        }
                        mma_bf16(acc[mf][nf], aa, bb);
                    }
        }

        CP_WAIT1();
        __syncthreads();
        cur = cur + 1; if (cur >= NSTAGE) cur -= NSTAGE;
    }
}

// ============================ HMMA GEMM kernels ==============================
__global__ __launch_bounds__(256, 1) void k_gemm_scores(const unsigned char* __restrict__ cmask) {
    extern __shared__ char sm[];
    const int b = blockIdx.z, i0 = blockIdx.y * 128, j0 = blockIdx.x * 128;
    const size_t aBase = ((size_t)b * LSEQ + i0) * DIM;
    const size_t bBase = ((size_t)b * LSEQ + j0) * DIM;
    float acc[4][4][4];
    gemm_tile<false>(g_c2_hi + aBase, g_c2_lo + aBase, DIM,
                     g_c1_hi + bBase, g_c1_lo + bBase, DIM, DIM / KC, sm, acc);

    const int w = threadIdx.x >> 5, lane = threadIdx.x & 31;
    const int wm = (w & 1) * 64, wn = (w >> 1) * 32;
#pragma unroll
    for (int mf = 0; mf < 4; mf++)
#pragma unroll
        for (int nf = 0; nf < 4; nf++) {
            const int gj = j0 + wn + nf * 8 + (lane & 3) * 2;
            const unsigned char m0 = cmask[b * LSEQ + gj];
            const unsigned char m1 = cmask[b * LSEQ + gj + 1];
#pragma unroll
            for (int half = 0; half < 2; half++) {
                const int gi = i0 + wm + mf * 16 + (lane >> 2) + half * 8;
                float2 v = make_float2(acc[mf][nf][2 * half], acc[mf][nf][2 * half + 1]);
                if (gi == gj || m0) v.x = -INFINITY;
                if (gi == gj + 1 || m1) v.y = -INFINITY;
                *(float2*)&g_scores[((size_t)(b * LSEQ) + gi) * LSEQ + gj] = v;
            }
        }
}

__global__ __launch_bounds__(256, 1) void k_gemm_aug() {
    extern __shared__ char sm[];
    const int b = blockIdx.z, i0 = blockIdx.y * 128, n0 = blockIdx.x * 128;
    const size_t aBase = ((size_t)b * LSEQ + i0) * LSEQ;
    const size_t bBase = ((size_t)b * DIM + n0) * LSEQ;
    float acc[4][4][4];
    gemm_tile<false>(g_alpha_hi + aBase, g_alpha_lo + aBase, LSEQ,
                     g_c1t_hi + bBase, g_c1t_lo + bBase, LSEQ, LSEQ / KC, sm, acc);

    const int w = threadIdx.x >> 5, lane = threadIdx.x & 31;
    const int wm = (w & 1) * 64, wn = (w >> 1) * 32;
#pragma unroll
    for (int mf = 0; mf < 4; mf++)
#pragma unroll
        for (int nf = 0; nf < 4; nf++) {
            const int gn = n0 + wn + nf * 8 + (lane & 3) * 2;
#pragma unroll
            for (int half = 0; half < 2; half++) {
                const int gi = i0 + wm + mf * 16 + (lane >> 2) + half * 8;
                float2 v = make_float2(acc[mf][nf][2 * half], acc[mf][nf][2 * half + 1]);
                *(float2*)&g_aug[((size_t)(b * LSEQ) + gi) * DIM + gn] = v;
            }
        }
}

// 2-pass: z (hi/lo pair) x Wf_hi (single bf16)
__global__ __launch_bounds__(256, 1) void k_gemm_fusion(const float* __restrict__ c2,
                                                        const float* __restrict__ bf,
                                                        float* __restrict__ out) {
    extern __shared__ char sm[];
    const int n0 = blockIdx.x * 128, m0 = blockIdx.y * 128;
    const size_t aBase = (size_t)m0 * (4 * DIM);
    const size_t bBase = (size_t)n0 * (4 * DIM);
    float acc[4][4][4];
    gemm_tile<true>(g_z_hi + aBase, g_z_lo + aBase, 4 * DIM,
                    g_wft_hi + bBase, g_wft_hi + bBase, 4 * DIM, (4 * DIM) / KC, sm, acc);

    const int w = threadIdx.x >> 5, lane = threadIdx.x & 31;
    const int wm = (w & 1) * 64, wn = (w >> 1) * 32;
#pragma unroll
    for (int mf = 0; mf < 4; mf++)
#pragma unroll
        for (int nf = 0; nf < 4; nf++) {
            const int col = n0 + wn + nf * 8 + (lane & 3) * 2;
            const float bf0 = bf[col], bf1 = bf[col + 1];
#pragma unroll
            for (int half = 0; half < 2; half++) {
                const int grow = m0 + wm + mf * 16 + (lane >> 2) + half * 8;
                const float g = g_gate[grow];
                const float2 cv = *(const float2*)&c2[(size_t)grow * DIM + col];
                float2 v;
                v.x = g * tanhf(acc[mf][nf][2 * half] + bf0) + (1.f - g) * cv.x;
                v.y = g * tanhf(acc[mf][nf][2 * half + 1] + bf1) + (1.f - g) * cv.y;
                *(float2*)&out[(size_t)grow * DIM + col] = v;
            }
        }
}

// ============================ softmax + alpha split ==========================
__global__ __launch_bounds__(256) void k_softmax() {
    const size_t row = blockIdx.x;
    const float4* p4 = (const float4*)(g_scores + row * LSEQ);
    const int t = threadIdx.x;
    const int lane = t & 31, wrp = t >> 5;

    float4 va = p4[2 * t];
    float4 vb = p4[2 * t + 1];

    float m = fmaxf(fmaxf(fmaxf(va.x, va.y), fmaxf(va.z, va.w)),
                    fmaxf(fmaxf(vb.x, vb.y), fmaxf(vb.z, vb.w)));
#pragma unroll
    for (int s = 16; s > 0; s >>= 1)
        m = fmaxf(m, __shfl_xor_sync(0xffffffffu, m, s));
    __shared__ float red[8];
    if (lane == 0) red[wrp] = m;
    __syncthreads();
    if (wrp == 0) {
        float x = red[lane & 7];
#pragma unroll
        for (int s = 4; s > 0; s >>= 1)
            x = fmaxf(x, __shfl_xor_sync(0xffffffffu, x, s));
        if (lane == 0) red[0] = x;
    }
    __syncthreads();
    m = red[0];

    va.x = __expf(va.x - m); va.y = __expf(va.y - m);
    va.z = __expf(va.z - m); va.w = __expf(va.w - m);
    vb.x = __expf(vb.x - m); vb.y = __expf(vb.y - m);
    vb.z = __expf(vb.z - m); vb.w = __expf(vb.w - m);
    float sum = (va.x + va.y + va.z + va.w) + (vb.x + vb.y + vb.z + vb.w);
#pragma unroll
    for (int s = 16; s > 0; s >>= 1)
        sum += __shfl_xor_sync(0xffffffffu, sum, s);
    __shared__ float red2[8];
    if (lane == 0) red2[wrp] = sum;
    __syncthreads();
    if (wrp == 0) {
        float x = red2[lane & 7];
#pragma unroll
        for (int s = 4; s > 0; s >>= 1)
            x += __shfl_xor_sync(0xffffffffu, x, s);
        if (lane == 0) red2[0] = x;
    }
    __syncthreads();
    const float inv = 1.f / red2[0];

    const size_t o = row * LSEQ + (size_t)t * 8;
    float vals[8] = {va.x * inv, va.y * inv, va.z * inv, va.w * inv,
                     vb.x * inv, vb.y * inv, vb.z * inv, vb.w * inv};
#pragma unroll
    for (int p = 0; p < 4; p++) {
        const float a0 = vals[2 * p], a1 = vals[2 * p + 1];
        const __nv_bfloat16 h0 = __float2bfloat16(a0);
        const __nv_bfloat16 h1 = __float2bfloat16(a1);
        __nv_bfloat162 hh; hh.x = h0; hh.y = h1;
        __nv_bfloat162 ll;
        ll.x = __float2bfloat16(a0 - __bfloat162float(h0));
        ll.y = __float2bfloat16(a1 - __bfloat162float(h1));
        *(__nv_bfloat162*)&g_alpha_hi[o + 2 * p] = hh;
        *(__nv_bfloat162*)&g_alpha_lo[o + 2 * p] = ll;
    }
}

// ============================ z prep + gate ==================================
__global__ __launch_bounds__(256) void k_prep_z(const float* __restrict__ c2,
                                                const float* __restrict__ Wg,
                                                const float* __restrict__ bg) {
    const int m = blockIdx.x;
    const int t = threadIdx.x;
    const float c2v = c2[(size_t)m * DIM + t];
    const float av  = g_aug[(size_t)m * DIM + t];
    const float z[4] = {c2v, av, c2v * av, c2v - av};
    float part = 0.f;
#pragma unroll
    for (int s = 0; s < 4; s++) {
        const size_t o = (size_t)m * (4 * DIM) + s * DIM + t;
        const __nv_bfloat16 h = __float2bfloat16(z[s]);
        g_z_hi[o] = h;
        g_z_lo[o] = __float2bfloat16(z[s] - __bfloat162float(h));
        part += z[s] * Wg[s * DIM + t];
    }
    __shared__ float red[256];
    red[t] = part;
    __syncthreads();
    for (int s = 128; s > 0; s >>= 1) {
        if (t < s) red[t] += red[t + s];
        __syncthreads();
    }
    if (t == 0) g_gate[m] = 1.f / (1.f + __expf(-(red[0] + bg[0])));
}

// ============================ launch =========================================
extern "C" void kernel_launch(void* const* d_in, const int* in_sizes, int n_in,
                              void* d_out, int out_size) {
    const float* c1 = (const float*)d_in[0];
    const float* c2 = (const float*)d_in[1];
    const unsigned char* cmask = (const unsigned char*)d_in[2];
    const float* Wf = (const float*)d_in[3];
    const float* bf = (const float*)d_in[4];
    const float* Wg = (const float*)d_in[5];
    const float* bg = (const float*)d_in[6];
    float* out = (float*)d_out;

    cudaFuncSetAttribute(k_gemm_scores, cudaFuncAttributeMaxDynamicSharedMemorySize, SMEM_DYN);
    cudaFuncSetAttribute(k_gemm_aug,    cudaFuncAttributeMaxDynamicSharedMemorySize, SMEM_DYN);
    cudaFuncSetAttribute(k_gemm_fusion, cudaFuncAttributeMaxDynamicSharedMemorySize, SMEM_DYN);

    k_prep_split<<<(BATCH * LSEQ * DIM) / 256, 256>>>(c1, c2);
    k_prep_t<<<dim3(LSEQ / 32, DIM / 32, BATCH), dim3(32, 8)>>>(c1);
    k_prep_wft<<<(DIM * 4 * DIM) / 256, 256>>>(Wf);

    k_gemm_scores<<<dim3(LSEQ / 128, LSEQ / 128, BATCH), 256, SMEM_DYN>>>(cmask);
    k_softmax<<<BATCH * LSEQ, 256>>>();
    k_gemm_aug<<<dim3(DIM / 128, LSEQ / 128, BATCH), 256, SMEM_DYN>>>();
    k_prep_z<<<BATCH * LSEQ, 256>>>(c2, Wg, bg);
    k_gemm_fusion<<<dim3(DIM / 128, (BATCH * LSEQ) / 128), 256, SMEM_DYN>>>(c2, bf, out);
}

// round 11
// speedup vs baseline: 1.5957x; 1.0445x over previous
#include <cuda_runtime.h>
#include <cuda_bf16.h>
#include <cstdint>
#include <math.h>

#define LSEQ 2048
#define DIM  256
#define BATCH 8
#define NJT  (LSEQ / 128)      // 16 j-tiles per row

#define KC 32
#define PAD_STR 40
#define TILE_B (128 * PAD_STR * 2)
#define STAGE_B (4 * TILE_B)
#define NSTAGE 3
#define SMEM_DYN (NSTAGE * STAGE_B)

#define EXP_SHIFT 80.0f

// ============================ PTX helpers ====================================
__device__ __forceinline__ uint32_t smem_to_u32(const void* p) {
    uint32_t a;
    asm("{ .reg .u64 t; cvta.to.shared.u64 t, %1; cvt.u32.u64 %0, t; }"
        : "=r"(a) : "l"(p));
    return a;
}
__device__ __forceinline__ void cp_async16(uint32_t dst, const void* src) {
    asm volatile("cp.async.cg.shared.global [%0], [%1], 16;" :: "r"(dst), "l"(src));
}
#define CP_COMMIT() asm volatile("cp.async.commit_group;" ::: "memory")
#define CP_WAIT1()  asm volatile("cp.async.wait_group 1;" ::: "memory")

__device__ __forceinline__ void ldsm_x4(uint32_t addr, uint32_t* r) {
    asm volatile("ldmatrix.sync.aligned.m8n8.x4.shared.b16 {%0,%1,%2,%3}, [%4];"
                 : "=r"(r[0]), "=r"(r[1]), "=r"(r[2]), "=r"(r[3]) : "r"(addr));
}
__device__ __forceinline__ void mma_bf16(float* c, const uint32_t* a, const uint32_t* b) {
    asm("mma.sync.aligned.m16n8k16.row.col.f32.bf16.bf16.f32 "
        "{%0,%1,%2,%3}, {%4,%5,%6,%7}, {%8,%9}, {%0,%1,%2,%3};"
        : "+f"(c[0]), "+f"(c[1]), "+f"(c[2]), "+f"(c[3])
        : "r"(a[0]), "r"(a[1]), "r"(a[2]), "r"(a[3]), "r"(b[0]), "r"(b[1]));
}

// ============================ device scratch =================================
static __device__ __nv_bfloat16 g_c1_hi[(size_t)BATCH * LSEQ * DIM];
static __device__ __nv_bfloat16 g_c1_lo[(size_t)BATCH * LSEQ * DIM];
static __device__ __nv_bfloat16 g_c2_hi[(size_t)BATCH * LSEQ * DIM];
static __device__ __nv_bfloat16 g_c2_lo[(size_t)BATCH * LSEQ * DIM];
static __device__ __nv_bfloat16 g_c1t_hi[(size_t)BATCH * DIM * LSEQ];
static __device__ __nv_bfloat16 g_c1t_lo[(size_t)BATCH * DIM * LSEQ];
static __device__ __nv_bfloat16 g_wft_hi[(size_t)DIM * 4 * DIM];   // [n=256][k=1024]
static __device__ __nv_bfloat16 g_alpha_hi[(size_t)BATCH * LSEQ * LSEQ];  // unnormalized exp
static __device__ __nv_bfloat16 g_alpha_lo[(size_t)BATCH * LSEQ * LSEQ];
static __device__ float         g_psum[(size_t)BATCH * LSEQ * NJT];       // per-tile row sums
static __device__ float         g_invS[BATCH * LSEQ];
static __device__ __nv_bfloat16 g_z_hi[(size_t)BATCH * LSEQ * 4 * DIM];
static __device__ __nv_bfloat16 g_z_lo[(size_t)BATCH * LSEQ * 4 * DIM];
static __device__ float         g_gateP[BATCH * LSEQ * 2];                // 2 n-block partials

// ============================ prep kernels ===================================
__global__ __launch_bounds__(256) void k_prep_split(const float* __restrict__ c1,
                                                    const float* __restrict__ c2) {
    size_t i = (size_t)blockIdx.x * 256 + threadIdx.x;
    if (i < (size_t)BATCH * LSEQ * DIM) {
        float v = c1[i];
        __nv_bfloat16 h = __float2bfloat16(v);
        g_c1_hi[i] = h;
        g_c1_lo[i] = __float2bfloat16(v - __bfloat162float(h));
        v = c2[i];
        h = __float2bfloat16(v);
        g_c2_hi[i] = h;
        g_c2_lo[i] = __float2bfloat16(v - __bfloat162float(h));
    }
}

__global__ __launch_bounds__(256) void k_prep_t(const float* __restrict__ c1) {
    __shared__ float tile[32][33];
    const int b = blockIdx.z;
    const int j0 = blockIdx.x * 32, d0 = blockIdx.y * 32;
    const float* src = c1 + (size_t)b * LSEQ * DIM;
    const int tx = threadIdx.x, ty = threadIdx.y;  // block (32, 8)
#pragma unroll
    for (int r = 0; r < 32; r += 8)
        tile[ty + r][tx] = src[(size_t)(j0 + ty + r) * DIM + d0 + tx];
    __syncthreads();
#pragma unroll
    for (int r = 0; r < 32; r += 8) {
        float v = tile[tx][ty + r];
        __nv_bfloat16 h = __float2bfloat16(v);
        size_t o = (size_t)b * DIM * LSEQ + (size_t)(d0 + ty + r) * LSEQ + j0 + tx;
        g_c1t_hi[o] = h;
        g_c1t_lo[o] = __float2bfloat16(v - __bfloat162float(h));
    }
}

__global__ __launch_bounds__(256) void k_prep_wft(const float* __restrict__ Wf) {
    int i = blockIdx.x * 256 + threadIdx.x;  // i = n*1024 + k
    if (i < DIM * 4 * DIM) {
        int n = i >> 10, k = i & 1023;
        g_wft_hi[i] = __float2bfloat16(Wf[(size_t)k * DIM + n]);
    }
}

// ============================ HMMA GEMM mainloop =============================
template <bool TWO_PASS>
__device__ __forceinline__ void load_chunk(uint32_t sbase,
                                           const __nv_bfloat16* __restrict__ Ah,
                                           const __nv_bfloat16* __restrict__ Al,
                                           size_t aStr,
                                           const __nv_bfloat16* __restrict__ Bh,
                                           const __nv_bfloat16* __restrict__ Bl,
                                           size_t bStr, int kOff) {
    const int t = threadIdx.x;
    const int c = (t & 3) * 8;
    const int r = t >> 2;
    const uint32_t soff = (uint32_t)(r * PAD_STR + c) * 2;
    const uint32_t soff2 = soff + 64 * PAD_STR * 2;
    {
        const __nv_bfloat16* g = Ah + (size_t)r * aStr + kOff + c;
        cp_async16(sbase + 0 * TILE_B + soff, g);
        cp_async16(sbase + 0 * TILE_B + soff2, g + 64 * aStr);
    }
    {
        const __nv_bfloat16* g = Al + (size_t)r * aStr + kOff + c;
        cp_async16(sbase + 1 * TILE_B + soff, g);
        cp_async16(sbase + 1 * TILE_B + soff2, g + 64 * aStr);
    }
    {
        const __nv_bfloat16* g = Bh + (size_t)r * bStr + kOff + c;
        cp_async16(sbase + 2 * TILE_B + soff, g);
        cp_async16(sbase + 2 * TILE_B + soff2, g + 64 * bStr);
    }
    if (!TWO_PASS) {
        const __nv_bfloat16* g = Bl + (size_t)r * bStr + kOff + c;
        cp_async16(sbase + 3 * TILE_B + soff, g);
        cp_async16(sbase + 3 * TILE_B + soff2, g + 64 * bStr);
    }
}

template <bool TWO_PASS>
__device__ __forceinline__ void gemm_tile(const __nv_bfloat16* __restrict__ Ah,
                                          const __nv_bfloat16* __restrict__ Al,
                                          size_t aStr,
                                          const __nv_bfloat16* __restrict__ Bh,
                                          const __nv_bfloat16* __restrict__ Bl,
                                          size_t bStr, int nChunks, char* sm,
                                          float acc[4][4][4]) {
    const int t = threadIdx.x;
    const int w = t >> 5, lane = t & 31;
    const int wm = (w & 1) * 64;
    const int wn = (w >> 1) * 32;
    const uint32_t smb = smem_to_u32(sm);

#pragma unroll
    for (int mf = 0; mf < 4; mf++)
#pragma unroll
        for (int nf = 0; nf < 4; nf++)
#pragma unroll
            for (int e = 0; e < 4; e++) acc[mf][nf][e] = 0.f;

    const int arow = wm + (lane & 15);
    const int acol = (lane >> 4) * 8;
    const int brow = wn + (lane & 7) + ((lane >> 4) ? 8 : 0);
    const int bcol = ((lane >> 3) & 1) * 8;

    load_chunk<TWO_PASS>(smb + 0 * STAGE_B, Ah, Al, aStr, Bh, Bl, bStr, 0);
    CP_COMMIT();
    load_chunk<TWO_PASS>(smb + 1 * STAGE_B, Ah, Al, aStr, Bh, Bl, bStr, KC);
    CP_COMMIT();
    CP_WAIT1();
    __syncthreads();

    int cur = 0;
    for (int kc = 0; kc < nChunks; kc++) {
        if (kc + 2 < nChunks) {
            int nxt = cur + 2; if (nxt >= NSTAGE) nxt -= NSTAGE;
            load_chunk<TWO_PASS>(smb + (uint32_t)nxt * STAGE_B, Ah, Al, aStr, Bh, Bl, bStr,
                                 (kc + 2) * KC);
        }
        CP_COMMIT();

        const uint32_t s = (uint32_t)cur * STAGE_B;
        const uint32_t sah = smb + s + 0 * TILE_B;
        const uint32_t sal = smb + s + 1 * TILE_B;
        const uint32_t sbh = smb + s + 2 * TILE_B;
        const uint32_t sbl = smb + s + 3 * TILE_B;

#pragma unroll
        for (int ks = 0; ks < 2; ks++) {
            const int k0 = ks * 16;
            uint32_t ah[4][4], al[4][4], bh[2][4], bl[2][4];
#pragma unroll
            for (int mf = 0; mf < 4; mf++) {
                const uint32_t off = (uint32_t)((arow + mf * 16) * PAD_STR + acol + k0) * 2;
                ldsm_x4(sah + off, ah[mf]);
                ldsm_x4(sal + off, al[mf]);
            }
#pragma unroll
            for (int nb = 0; nb < 2; nb++) {
                const uint32_t off = (uint32_t)((brow + nb * 16) * PAD_STR + bcol + k0) * 2;
                ldsm_x4(sbh + off, bh[nb]);
                if (!TWO_PASS) ldsm_x4(sbl + off, bl[nb]);
            }
            const int NP = TWO_PASS ? 2 : 3;
#pragma unroll
            for (int p = 0; p < NP; p++)
#pragma unroll
                for (int mf = 0; mf < 4; mf++)
#pragma unroll
                    for (int nf = 0; nf < 4; nf++) {
                        const uint32_t* aa;
                        const uint32_t* bb;
                        if (TWO_PASS) {
                            aa = (p == 1) ? al[mf] : ah[mf];
                            bb = &bh[nf >> 1][(nf & 1) * 2];
                        } else {
                            aa = (p == 2) ? al[mf] : ah[mf];
                            bb = (p == 1) ? &bl[nf >> 1][(nf & 1) * 2]
                                          : &bh[nf >> 1][(nf & 1) * 2];
                        }
                        mma_bf16(acc[mf][nf], aa, bb);
                    }
        }

        CP_WAIT1();
        __syncthreads();
        cur = cur + 1; if (cur >= NSTAGE) cur -= NSTAGE;
    }
}

// ============================ scores kernel ==================================
// epilogue: e = exp(score - 80) (masked -> 0), written as hi/lo bf16 alpha,
// plus per-tile row sums into g_psum[row][jt].
__global__ __launch_bounds__(256, 1) void k_gemm_scores(const unsigned char* __restrict__ cmask) {
    extern __shared__ char sm[];
    const int b = blockIdx.z, i0 = blockIdx.y * 128, j0 = blockIdx.x * 128;
    const size_t aBase = ((size_t)b * LSEQ + i0) * DIM;
    const size_t bBase = ((size_t)b * LSEQ + j0) * DIM;
    float acc[4][4][4];
    gemm_tile<false>(g_c2_hi + aBase, g_c2_lo + aBase, DIM,
                     g_c1_hi + bBase, g_c1_lo + bBase, DIM, DIM / KC, sm, acc);

    const int t = threadIdx.x;
    const int w = t >> 5, lane = t & 31;
    const int wm = (w & 1) * 64, wn = (w >> 1) * 32;

    float rsum[4][2];
#pragma unroll
    for (int mf = 0; mf < 4; mf++) { rsum[mf][0] = 0.f; rsum[mf][1] = 0.f; }

#pragma unroll
    for (int mf = 0; mf < 4; mf++)
#pragma unroll
        for (int nf = 0; nf < 4; nf++) {
            const int gj = j0 + wn + nf * 8 + (lane & 3) * 2;
            const unsigned char mk0 = cmask[b * LSEQ + gj];
            const unsigned char mk1 = cmask[b * LSEQ + gj + 1];
#pragma unroll
            for (int half = 0; half < 2; half++) {
                const int gi = i0 + wm + mf * 16 + (lane >> 2) + half * 8;
                const float e0 = (gi == gj || mk0) ? 0.f
                               : __expf(acc[mf][nf][2 * half] - EXP_SHIFT);
                const float e1 = (gi == gj + 1 || mk1) ? 0.f
                               : __expf(acc[mf][nf][2 * half + 1] - EXP_SHIFT);
                const __nv_bfloat16 h0 = __float2bfloat16(e0);
                const __nv_bfloat16 h1 = __float2bfloat16(e1);
                __nv_bfloat162 hh; hh.x = h0; hh.y = h1;
                __nv_bfloat162 ll;
                ll.x = __float2bfloat16(e0 - __bfloat162float(h0));
                ll.y = __float2bfloat16(e1 - __bfloat162float(h1));
                const size_t o = ((size_t)(b * LSEQ) + gi) * LSEQ + gj;
                *(__nv_bfloat162*)&g_alpha_hi[o] = hh;
                *(__nv_bfloat162*)&g_alpha_lo[o] = ll;
                rsum[mf][half] += e0 + e1;
            }
        }

    // quad reduce (4 lanes per row-slice), then cross-warp via smem
    float* sred = (float*)sm;   // 512 floats; mainloop smem is free post-sync
#pragma unroll
    for (int mf = 0; mf < 4; mf++)
#pragma unroll
        for (int half = 0; half < 2; half++) {
            float r = rsum[mf][half];
            r += __shfl_xor_sync(0xffffffffu, r, 1);
            r += __shfl_xor_sync(0xffffffffu, r, 2);
            if ((lane & 3) == 0) {
                const int rowl = wm + mf * 16 + (lane >> 2) + half * 8;
                sred[(w >> 1) * 128 + rowl] = r;
            }
        }
    __syncthreads();
    if (t < 128) {
        const float S = sred[t] + sred[128 + t] + sred[256 + t] + sred[384 + t];
        g_psum[((size_t)(b * LSEQ) + i0 + t) * NJT + blockIdx.x] = S;
    }
}

// ============================ invS reduce ====================================
__global__ __launch_bounds__(256) void k_reduce_invS() {
    const int row = blockIdx.x * 256 + threadIdx.x;   // 16384 rows
    const float4* p = (const float4*)(g_psum + (size_t)row * NJT);
    float4 a = p[0], bq = p[1], c = p[2], d = p[3];
    const float S = (a.x + a.y + a.z + a.w) + (bq.x + bq.y + bq.z + bq.w) +
                    (c.x + c.y + c.z + c.w) + (d.x + d.y + d.z + d.w);
    g_invS[row] = 1.f / S;
}

// ============================ aug kernel ====================================
// epilogue: scale by invS, build z hi/lo (4 segments) + gate partials.
__global__ __launch_bounds__(256, 1) void k_gemm_aug(const float* __restrict__ c2,
                                                     const float* __restrict__ Wg) {
    extern __shared__ char sm[];
    const int b = blockIdx.z, i0 = blockIdx.y * 128, n0 = blockIdx.x * 128;
    const size_t aBase = ((size_t)b * LSEQ + i0) * LSEQ;
    const size_t bBase = ((size_t)b * DIM + n0) * LSEQ;
    float acc[4][4][4];
    gemm_tile<false>(g_alpha_hi + aBase, g_alpha_lo + aBase, LSEQ,
                     g_c1t_hi + bBase, g_c1t_lo + bBase, LSEQ, LSEQ / KC, sm, acc);

    const int t = threadIdx.x;
    const int w = t >> 5, lane = t & 31;
    const int wm = (w & 1) * 64, wn = (w >> 1) * 32;

    float gsum[4][2];
#pragma unroll
    for (int mf = 0; mf < 4; mf++) { gsum[mf][0] = 0.f; gsum[mf][1] = 0.f; }

#pragma unroll
    for (int mf = 0; mf < 4; mf++)
#pragma unroll
        for (int half = 0; half < 2; half++) {
            const int gi = i0 + wm + mf * 16 + (lane >> 2) + half * 8;
            const size_t grow = (size_t)(b * LSEQ) + gi;
            const float invS = g_invS[grow];
#pragma unroll
            for (int nf = 0; nf < 4; nf++) {
                const int gn = n0 + wn + nf * 8 + (lane & 3) * 2;
                const float a0 = acc[mf][nf][2 * half] * invS;
                const float a1 = acc[mf][nf][2 * half + 1] * invS;
                const float2 cv = *(const float2*)&c2[grow * DIM + gn];
                const float z0[4] = {cv.x, a0, cv.x * a0, cv.x - a0};
                const float z1[4] = {cv.y, a1, cv.y * a1, cv.y - a1};
#pragma unroll
                for (int s = 0; s < 4; s++) {
                    const int col = s * DIM + gn;
                    const __nv_bfloat16 h0 = __float2bfloat16(z0[s]);
                    const __nv_bfloat16 h1 = __float2bfloat16(z1[s]);
                    __nv_bfloat162 hh; hh.x = h0; hh.y = h1;
                    __nv_bfloat162 ll;
                    ll.x = __float2bfloat16(z0[s] - __bfloat162float(h0));
                    ll.y = __float2bfloat16(z1[s] - __bfloat162float(h1));
                    const size_t o = grow * (4 * DIM) + col;
                    *(__nv_bfloat162*)&g_z_hi[o] = hh;
                    *(__nv_bfloat162*)&g_z_lo[o] = ll;
                    gsum[mf][half] += z0[s] * Wg[col] + z1[s] * Wg[col + 1];
                }
            }
        }

    float* sred = (float*)sm;
#pragma unroll
    for (int mf = 0; mf < 4; mf++)
#pragma unroll
        for (int half = 0; half < 2; half++) {
            float r = gsum[mf][half];
            r += __shfl_xor_sync(0xffffffffu, r, 1);
            r += __shfl_xor_sync(0xffffffffu, r, 2);
            if ((lane & 3) == 0) {
                const int rowl = wm + mf * 16 + (lane >> 2) + half * 8;
                sred[(w >> 1) * 128 + rowl] = r;
            }
        }
    __syncthreads();
    if (t < 128) {
        const float gp = sred[t] + sred[128 + t] + sred[256 + t] + sred[384 + t];
        g_gateP[((size_t)(b * LSEQ) + i0 + t) * 2 + (n0 >> 7)] = gp;
    }
}

// ============================ fusion kernel ==================================
__global__ __launch_bounds__(256, 1) void k_gemm_fusion(const float* __restrict__ c2,
                                                        const float* __restrict__ bf,
                                                        const float* __restrict__ bg,
                                                        float* __restrict__ out) {
    extern __shared__ char sm[];
    const int n0 = blockIdx.x * 128, m0 = blockIdx.y * 128;
    const size_t aBase = (size_t)m0 * (4 * DIM);
    const size_t bBase = (size_t)n0 * (4 * DIM);
    float acc[4][4][4];
    gemm_tile<true>(g_z_hi + aBase, g_z_lo + aBase, 4 * DIM,
                    g_wft_hi + bBase, g_wft_hi + bBase, 4 * DIM, (4 * DIM) / KC, sm, acc);

    const int w = threadIdx.x >> 5, lane = threadIdx.x & 31;
    const int wm = (w & 1) * 64, wn = (w >> 1) * 32;
    const float bgv = bg[0];
#pragma unroll
    for (int mf = 0; mf < 4; mf++)
#pragma unroll
        for (int half = 0; half < 2; half++) {
            const int grow = m0 + wm + mf * 16 + (lane >> 2) + half * 8;
            const float gp = g_gateP[(size_t)grow * 2] + g_gateP[(size_t)grow * 2 + 1];
            const float g = 1.f / (1.f + __expf(-(gp + bgv)));
#pragma unroll
            for (int nf = 0; nf < 4; nf++) {
                const int col = n0 + wn + nf * 8 + (lane & 3) * 2;
                const float bf0 = bf[col], bf1 = bf[col + 1];
                const float2 cv = *(const float2*)&c2[(size_t)grow * DIM + col];
                float2 v;
                v.x = g * tanhf(acc[mf][nf][2 * half] + bf0) + (1.f - g) * cv.x;
                v.y = g * tanhf(acc[mf][nf][2 * half + 1] + bf1) + (1.f - g) * cv.y;
                *(float2*)&out[(size_t)grow * DIM + col] = v;
            }
        }
}

// ============================ launch =========================================
extern "C" void kernel_launch(void* const* d_in, const int* in_sizes, int n_in,
                              void* d_out, int out_size) {
    const float* c1 = (const float*)d_in[0];
    const float* c2 = (const float*)d_in[1];
    const unsigned char* cmask = (const unsigned char*)d_in[2];
    const float* Wf = (const float*)d_in[3];
    const float* bf = (const float*)d_in[4];
    const float* Wg = (const float*)d_in[5];
    const float* bg = (const float*)d_in[6];
    float* out = (float*)d_out;

    cudaFuncSetAttribute(k_gemm_scores, cudaFuncAttributeMaxDynamicSharedMemorySize, SMEM_DYN);
    cudaFuncSetAttribute(k_gemm_aug,    cudaFuncAttributeMaxDynamicSharedMemorySize, SMEM_DYN);
    cudaFuncSetAttribute(k_gemm_fusion, cudaFuncAttributeMaxDynamicSharedMemorySize, SMEM_DYN);

    k_prep_split<<<(BATCH * LSEQ * DIM) / 256, 256>>>(c1, c2);
    k_prep_t<<<dim3(LSEQ / 32, DIM / 32, BATCH), dim3(32, 8)>>>(c1);
    k_prep_wft<<<(DIM * 4 * DIM) / 256, 256>>>(Wf);

    k_gemm_scores<<<dim3(NJT, LSEQ / 128, BATCH), 256, SMEM_DYN>>>(cmask);
    k_reduce_invS<<<(BATCH * LSEQ) / 256, 256>>>();
    k_gemm_aug<<<dim3(DIM / 128, LSEQ / 128, BATCH), 256, SMEM_DYN>>>(c2, Wg);
    k_gemm_fusion<<<dim3(DIM / 128, (BATCH * LSEQ) / 128), 256, SMEM_DYN>>>(c2, bf, bg, out);
}

// round 12
// speedup vs baseline: 1.6278x; 1.0201x over previous
#include <cuda_runtime.h>
#include <cuda_bf16.h>
#include <cstdint>
#include <math.h>

#define LSEQ 2048
#define DIM  256
#define BATCH 8
#define NJT  (LSEQ / 128)      // 16 j-tiles per row

#define KC 32
#define PAD_STR 40
#define TILE_B (128 * PAD_STR * 2)
#define STAGE_B (4 * TILE_B)
#define NSTAGE 3
#define SMEM_DYN (NSTAGE * STAGE_B)

#define EXP_SHIFT 80.0f

// ============================ PTX helpers ====================================
__device__ __forceinline__ uint32_t smem_to_u32(const void* p) {
    uint32_t a;
    asm("{ .reg .u64 t; cvta.to.shared.u64 t, %1; cvt.u32.u64 %0, t; }"
        : "=r"(a) : "l"(p));
    return a;
}
__device__ __forceinline__ void cp_async16(uint32_t dst, const void* src) {
    asm volatile("cp.async.cg.shared.global [%0], [%1], 16;" :: "r"(dst), "l"(src));
}
#define CP_COMMIT() asm volatile("cp.async.commit_group;" ::: "memory")
#define CP_WAIT1()  asm volatile("cp.async.wait_group 1;" ::: "memory")

__device__ __forceinline__ void ldsm_x4(uint32_t addr, uint32_t* r) {
    asm volatile("ldmatrix.sync.aligned.m8n8.x4.shared.b16 {%0,%1,%2,%3}, [%4];"
                 : "=r"(r[0]), "=r"(r[1]), "=r"(r[2]), "=r"(r[3]) : "r"(addr));
}
__device__ __forceinline__ void mma_bf16(float* c, const uint32_t* a, const uint32_t* b) {
    asm("mma.sync.aligned.m16n8k16.row.col.f32.bf16.bf16.f32 "
        "{%0,%1,%2,%3}, {%4,%5,%6,%7}, {%8,%9}, {%0,%1,%2,%3};"
        : "+f"(c[0]), "+f"(c[1]), "+f"(c[2]), "+f"(c[3])
        : "r"(a[0]), "r"(a[1]), "r"(a[2]), "r"(a[3]), "r"(b[0]), "r"(b[1]));
}

// packed hi/lo split: one rn-packed cvt per pair, readback is a shift
__device__ __forceinline__ void split_pair(float v0, float v1,
                                           __nv_bfloat162& hh, __nv_bfloat162& ll) {
    hh = __floats2bfloat162_rn(v0, v1);
    const float f0 = __bfloat162float(hh.x);
    const float f1 = __bfloat162float(hh.y);
    ll = __floats2bfloat162_rn(v0 - f0, v1 - f1);
}

// ============================ device scratch =================================
static __device__ __nv_bfloat16 g_c1_hi[(size_t)BATCH * LSEQ * DIM];
static __device__ __nv_bfloat16 g_c1_lo[(size_t)BATCH * LSEQ * DIM];
static __device__ __nv_bfloat16 g_c2_hi[(size_t)BATCH * LSEQ * DIM];
static __device__ __nv_bfloat16 g_c2_lo[(size_t)BATCH * LSEQ * DIM];
static __device__ __nv_bfloat16 g_c1t_hi[(size_t)BATCH * DIM * LSEQ];
static __device__ __nv_bfloat16 g_c1t_lo[(size_t)BATCH * DIM * LSEQ];
static __device__ __nv_bfloat16 g_wft_hi[(size_t)DIM * 4 * DIM];   // [n=256][k=1024]
static __device__ __nv_bfloat16 g_alpha_hi[(size_t)BATCH * LSEQ * LSEQ];  // unnormalized exp
static __device__ __nv_bfloat16 g_alpha_lo[(size_t)BATCH * LSEQ * LSEQ];
static __device__ float         g_psum[(size_t)BATCH * LSEQ * NJT];       // per-tile row sums
static __device__ float         g_invS[BATCH * LSEQ];
static __device__ __nv_bfloat16 g_z_hi[(size_t)BATCH * LSEQ * 4 * DIM];
static __device__ __nv_bfloat16 g_z_lo[(size_t)BATCH * LSEQ * 4 * DIM];
static __device__ float         g_gateP[BATCH * LSEQ * 2];                // 2 n-block partials

// ============================ prep kernels ===================================
__global__ __launch_bounds__(256) void k_prep_split(const float* __restrict__ c1,
                                                    const float* __restrict__ c2) {
    const size_t p = (size_t)blockIdx.x * 256 + threadIdx.x;   // pair index
    if (p < (size_t)BATCH * LSEQ * DIM / 2) {
        const float2 v1 = ((const float2*)c1)[p];
        const float2 v2 = ((const float2*)c2)[p];
        __nv_bfloat162 hh, ll;
        split_pair(v1.x, v1.y, hh, ll);
        ((__nv_bfloat162*)g_c1_hi)[p] = hh;
        ((__nv_bfloat162*)g_c1_lo)[p] = ll;
        split_pair(v2.x, v2.y, hh, ll);
        ((__nv_bfloat162*)g_c2_hi)[p] = hh;
        ((__nv_bfloat162*)g_c2_lo)[p] = ll;
    }
}

// transpose 32d x 64j tiles; packed bf162 stores along contiguous j
__global__ __launch_bounds__(256) void k_prep_t(const float* __restrict__ c1) {
    __shared__ float tile[64][33];
    const int b = blockIdx.z;
    const int j0 = blockIdx.x * 64, d0 = blockIdx.y * 32;
    const float* src = c1 + (size_t)b * LSEQ * DIM;
    const int tx = threadIdx.x, ty = threadIdx.y;  // block (32, 8)
#pragma unroll
    for (int r = 0; r < 64; r += 8)
        tile[ty + r][tx] = src[(size_t)(j0 + ty + r) * DIM + d0 + tx];
    __syncthreads();
#pragma unroll
    for (int r = 0; r < 32; r += 8) {
        const int d = ty + r;
        const float v0 = tile[2 * tx][d];
        const float v1 = tile[2 * tx + 1][d];
        __nv_bfloat162 hh, ll;
        split_pair(v0, v1, hh, ll);
        const size_t o = (size_t)b * DIM * LSEQ + (size_t)(d0 + d) * LSEQ + j0 + 2 * tx;
        *(__nv_bfloat162*)&g_c1t_hi[o] = hh;
        *(__nv_bfloat162*)&g_c1t_lo[o] = ll;
    }
}

__global__ __launch_bounds__(256) void k_prep_wft(const float* __restrict__ Wf) {
    int i = blockIdx.x * 256 + threadIdx.x;  // i = n*1024 + k
    if (i < DIM * 4 * DIM) {
        int n = i >> 10, k = i & 1023;
        g_wft_hi[i] = __float2bfloat16(Wf[(size_t)k * DIM + n]);
    }
}

// ============================ HMMA GEMM mainloop =============================
template <bool TWO_PASS>
__device__ __forceinline__ void load_chunk(uint32_t sbase,
                                           const __nv_bfloat16* __restrict__ Ah,
                                           const __nv_bfloat16* __restrict__ Al,
                                           size_t aStr,
                                           const __nv_bfloat16* __restrict__ Bh,
                                           const __nv_bfloat16* __restrict__ Bl,
                                           size_t bStr, int kOff) {
    const int t = threadIdx.x;
    const int c = (t & 3) * 8;
    const int r = t >> 2;
    const uint32_t soff = (uint32_t)(r * PAD_STR + c) * 2;
    const uint32_t soff2 = soff + 64 * PAD_STR * 2;
    {
        const __nv_bfloat16* g = Ah + (size_t)r * aStr + kOff + c;
        cp_async16(sbase + 0 * TILE_B + soff, g);
        cp_async16(sbase + 0 * TILE_B + soff2, g + 64 * aStr);
    }
    {
        const __nv_bfloat16* g = Al + (size_t)r * aStr + kOff + c;
        cp_async16(sbase + 1 * TILE_B + soff, g);
        cp_async16(sbase + 1 * TILE_B + soff2, g + 64 * aStr);
    }
    {
        const __nv_bfloat16* g = Bh + (size_t)r * bStr + kOff + c;
        cp_async16(sbase + 2 * TILE_B + soff, g);
        cp_async16(sbase + 2 * TILE_B + soff2, g + 64 * bStr);
    }
    if (!TWO_PASS) {
        const __nv_bfloat16* g = Bl + (size_t)r * bStr + kOff + c;
        cp_async16(sbase + 3 * TILE_B + soff, g);
        cp_async16(sbase + 3 * TILE_B + soff2, g + 64 * bStr);
    }
}

template <bool TWO_PASS>
__device__ __forceinline__ void gemm_tile(const __nv_bfloat16* __restrict__ Ah,
                                          const __nv_bfloat16* __restrict__ Al,
                                          size_t aStr,
                                          const __nv_bfloat16* __restrict__ Bh,
                                          const __nv_bfloat16* __restrict__ Bl,
                                          size_t bStr, int nChunks, char* sm,
                                          float acc[4][4][4]) {
    const int t = threadIdx.x;
    const int w = t >> 5, lane = t & 31;
    const int wm = (w & 1) * 64;
    const int wn = (w >> 1) * 32;
    const uint32_t smb = smem_to_u32(sm);

#pragma unroll
    for (int mf = 0; mf < 4; mf++)
#pragma unroll
        for (int nf = 0; nf < 4; nf++)
#pragma unroll
            for (int e = 0; e < 4; e++) acc[mf][nf][e] = 0.f;

    const int arow = wm + (lane & 15);
    const int acol = (lane >> 4) * 8;
    const int brow = wn + (lane & 7) + ((lane >> 4) ? 8 : 0);
    const int bcol = ((lane >> 3) & 1) * 8;

    load_chunk<TWO_PASS>(smb + 0 * STAGE_B, Ah, Al, aStr, Bh, Bl, bStr, 0);
    CP_COMMIT();
    load_chunk<TWO_PASS>(smb + 1 * STAGE_B, Ah, Al, aStr, Bh, Bl, bStr, KC);
    CP_COMMIT();
    CP_WAIT1();
    __syncthreads();

    int cur = 0;
    for (int kc = 0; kc < nChunks; kc++) {
        if (kc + 2 < nChunks) {
            int nxt = cur + 2; if (nxt >= NSTAGE) nxt -= NSTAGE;
            load_chunk<TWO_PASS>(smb + (uint32_t)nxt * STAGE_B, Ah, Al, aStr, Bh, Bl, bStr,
                                 (kc + 2) * KC);
        }
        CP_COMMIT();

        const uint32_t s = (uint32_t)cur * STAGE_B;
        const uint32_t sah = smb + s + 0 * TILE_B;
        const uint32_t sal = smb + s + 1 * TILE_B;
        const uint32_t sbh = smb + s + 2 * TILE_B;
        const uint32_t sbl = smb + s + 3 * TILE_B;

#pragma unroll
        for (int ks = 0; ks < 2; ks++) {
            const int k0 = ks * 16;
            uint32_t ah[4][4], al[4][4], bh[2][4], bl[2][4];
#pragma unroll
            for (int mf = 0; mf < 4; mf++) {
                const uint32_t off = (uint32_t)((arow + mf * 16) * PAD_STR + acol + k0) * 2;
                ldsm_x4(sah + off, ah[mf]);
                ldsm_x4(sal + off, al[mf]);
            }
#pragma unroll
            for (int nb = 0; nb < 2; nb++) {
                const uint32_t off = (uint32_t)((brow + nb * 16) * PAD_STR + bcol + k0) * 2;
                ldsm_x4(sbh + off, bh[nb]);
                if (!TWO_PASS) ldsm_x4(sbl + off, bl[nb]);
            }
            const int NP = TWO_PASS ? 2 : 3;
#pragma unroll
            for (int p = 0; p < NP; p++)
#pragma unroll
                for (int mf = 0; mf < 4; mf++)
#pragma unroll
                    for (int nf = 0; nf < 4; nf++) {
                        const uint32_t* aa;
                        const uint32_t* bb;
                        if (TWO_PASS) {
                            aa = (p == 1) ? al[mf] : ah[mf];
                            bb = &bh[nf >> 1][(nf & 1) * 2];
                        } else {
                            aa = (p == 2) ? al[mf] : ah[mf];
                            bb = (p == 1) ? &bl[nf >> 1][(nf & 1) * 2]
                                          : &bh[nf >> 1][(nf & 1) * 2];
                        }
                        mma_bf16(acc[mf][nf], aa, bb);
                    }
        }

        CP_WAIT1();
        __syncthreads();
        cur = cur + 1; if (cur >= NSTAGE) cur -= NSTAGE;
    }
}

// ============================ scores kernel ==================================
__global__ __launch_bounds__(256, 1) void k_gemm_scores(const unsigned char* __restrict__ cmask) {
    extern __shared__ char sm[];
    const int b = blockIdx.z, i0 = blockIdx.y * 128, j0 = blockIdx.x * 128;
    const size_t aBase = ((size_t)b * LSEQ + i0) * DIM;
    const size_t bBase = ((size_t)b * LSEQ + j0) * DIM;
    float acc[4][4][4];
    gemm_tile<false>(g_c2_hi + aBase, g_c2_lo + aBase, DIM,
                     g_c1_hi + bBase, g_c1_lo + bBase, DIM, DIM / KC, sm, acc);

    const int t = threadIdx.x;
    const int w = t >> 5, lane = t & 31;
    const int wm = (w & 1) * 64, wn = (w >> 1) * 32;
    const bool diagTile = (blockIdx.x == blockIdx.y);

    float rsum[4][2];
#pragma unroll
    for (int mf = 0; mf < 4; mf++) { rsum[mf][0] = 0.f; rsum[mf][1] = 0.f; }

#pragma unroll
    for (int mf = 0; mf < 4; mf++)
#pragma unroll
        for (int nf = 0; nf < 4; nf++) {
            const int gj = j0 + wn + nf * 8 + (lane & 3) * 2;
            const unsigned char mk0 = cmask[b * LSEQ + gj];
            const unsigned char mk1 = cmask[b * LSEQ + gj + 1];
#pragma unroll
            for (int half = 0; half < 2; half++) {
                const int gi = i0 + wm + mf * 16 + (lane >> 2) + half * 8;
                float e0 = __expf(acc[mf][nf][2 * half] - EXP_SHIFT);
                float e1 = __expf(acc[mf][nf][2 * half + 1] - EXP_SHIFT);
                if (mk0 || (diagTile && gi == gj)) e0 = 0.f;
                if (mk1 || (diagTile && gi == gj + 1)) e1 = 0.f;
                __nv_bfloat162 hh, ll;
                split_pair(e0, e1, hh, ll);
                const size_t o = ((size_t)(b * LSEQ) + gi) * LSEQ + gj;
                *(__nv_bfloat162*)&g_alpha_hi[o] = hh;
                *(__nv_bfloat162*)&g_alpha_lo[o] = ll;
                rsum[mf][half] += e0 + e1;
            }
        }

    float* sred = (float*)sm;
#pragma unroll
    for (int mf = 0; mf < 4; mf++)
#pragma unroll
        for (int half = 0; half < 2; half++) {
            float r = rsum[mf][half];
            r += __shfl_xor_sync(0xffffffffu, r, 1);
            r += __shfl_xor_sync(0xffffffffu, r, 2);
            if ((lane & 3) == 0) {
                const int rowl = wm + mf * 16 + (lane >> 2) + half * 8;
                sred[(w >> 1) * 128 + rowl] = r;
            }
        }
    __syncthreads();
    if (t < 128) {
        const float S = sred[t] + sred[128 + t] + sred[256 + t] + sred[384 + t];
        g_psum[((size_t)(b * LSEQ) + i0 + t) * NJT + blockIdx.x] = S;
    }
}

// ============================ invS reduce ====================================
__global__ __launch_bounds__(256) void k_reduce_invS() {
    const int row = blockIdx.x * 256 + threadIdx.x;   // 16384 rows
    const float4* p = (const float4*)(g_psum + (size_t)row * NJT);
    float4 a = p[0], bq = p[1], c = p[2], d = p[3];
    const float S = (a.x + a.y + a.z + a.w) + (bq.x + bq.y + bq.z + bq.w) +
                    (c.x + c.y + c.z + c.w) + (d.x + d.y + d.z + d.w);
    g_invS[row] = 1.f / S;
}

// ============================ aug kernel ====================================
__global__ __launch_bounds__(256, 1) void k_gemm_aug(const float* __restrict__ c2,
                                                     const float* __restrict__ Wg) {
    extern __shared__ char sm[];
    const int b = blockIdx.z, i0 = blockIdx.y * 128, n0 = blockIdx.x * 128;
    const size_t aBase = ((size_t)b * LSEQ + i0) * LSEQ;
    const size_t bBase = ((size_t)b * DIM + n0) * LSEQ;
    float acc[4][4][4];
    gemm_tile<false>(g_alpha_hi + aBase, g_alpha_lo + aBase, LSEQ,
                     g_c1t_hi + bBase, g_c1t_lo + bBase, LSEQ, LSEQ / KC, sm, acc);

    const int t = threadIdx.x;
    const int w = t >> 5, lane = t & 31;
    const int wm = (w & 1) * 64, wn = (w >> 1) * 32;

    float gsum[4][2];
#pragma unroll
    for (int mf = 0; mf < 4; mf++) { gsum[mf][0] = 0.f; gsum[mf][1] = 0.f; }

#pragma unroll
    for (int mf = 0; mf < 4; mf++)
#pragma unroll
        for (int half = 0; half < 2; half++) {
            const int gi = i0 + wm + mf * 16 + (lane >> 2) + half * 8;
            const size_t grow = (size_t)(b * LSEQ) + gi;
            const float invS = g_invS[grow];
#pragma unroll
            for (int nf = 0; nf < 4; nf++) {
                const int gn = n0 + wn + nf * 8 + (lane & 3) * 2;
                const float a0 = acc[mf][nf][2 * half] * invS;
                const float a1 = acc[mf][nf][2 * half + 1] * invS;
                const float2 cv = *(const float2*)&c2[grow * DIM + gn];
                const float z0[4] = {cv.x, a0, cv.x * a0, cv.x - a0};
                const float z1[4] = {cv.y, a1, cv.y * a1, cv.y - a1};
#pragma unroll
                for (int s = 0; s < 4; s++) {
                    const int col = s * DIM + gn;
                    __nv_bfloat162 hh, ll;
                    split_pair(z0[s], z1[s], hh, ll);
                    const size_t o = grow * (4 * DIM) + col;
                    *(__nv_bfloat162*)&g_z_hi[o] = hh;
                    *(__nv_bfloat162*)&g_z_lo[o] = ll;
                    gsum[mf][half] += z0[s] * Wg[col] + z1[s] * Wg[col + 1];
                }
            }
        }

    float* sred = (float*)sm;
#pragma unroll
    for (int mf = 0; mf < 4; mf++)
#pragma unroll
        for (int half = 0; half < 2; half++) {
            float r = gsum[mf][half];
            r += __shfl_xor_sync(0xffffffffu, r, 1);
            r += __shfl_xor_sync(0xffffffffu, r, 2);
            if ((lane & 3) == 0) {
                const int rowl = wm + mf * 16 + (lane >> 2) + half * 8;
                sred[(w >> 1) * 128 + rowl] = r;
            }
        }
    __syncthreads();
    if (t < 128) {
        const float gp = sred[t] + sred[128 + t] + sred[256 + t] + sred[384 + t];
        g_gateP[((size_t)(b * LSEQ) + i0 + t) * 2 + (n0 >> 7)] = gp;
    }
}

// ============================ fusion kernel ==================================
__global__ __launch_bounds__(256, 1) void k_gemm_fusion(const float* __restrict__ c2,
                                                        const float* __restrict__ bf,
                                                        const float* __restrict__ bg,
                                                        float* __restrict__ out) {
    extern __shared__ char sm[];
    const int n0 = blockIdx.x * 128, m0 = blockIdx.y * 128;
    const size_t aBase = (size_t)m0 * (4 * DIM);
    const size_t bBase = (size_t)n0 * (4 * DIM);
    float acc[4][4][4];
    gemm_tile<true>(g_z_hi + aBase, g_z_lo + aBase, 4 * DIM,
                    g_wft_hi + bBase, g_wft_hi + bBase, 4 * DIM, (4 * DIM) / KC, sm, acc);

    const int w = threadIdx.x >> 5, lane = threadIdx.x & 31;
    const int wm = (w & 1) * 64, wn = (w >> 1) * 32;
    const float bgv = bg[0];
#pragma unroll
    for (int mf = 0; mf < 4; mf++)
#pragma unroll
        for (int half = 0; half < 2; half++) {
            const int grow = m0 + wm + mf * 16 + (lane >> 2) + half * 8;
            const float gp = g_gateP[(size_t)grow * 2] + g_gateP[(size_t)grow * 2 + 1];
            const float g = 1.f / (1.f + __expf(-(gp + bgv)));
#pragma unroll
            for (int nf = 0; nf < 4; nf++) {
                const int col = n0 + wn + nf * 8 + (lane & 3) * 2;
                const float bf0 = bf[col], bf1 = bf[col + 1];
                const float2 cv = *(const float2*)&c2[(size_t)grow * DIM + col];
                float2 v;
                v.x = g * tanhf(acc[mf][nf][2 * half] + bf0) + (1.f - g) * cv.x;
                v.y = g * tanhf(acc[mf][nf][2 * half + 1] + bf1) + (1.f - g) * cv.y;
                *(float2*)&out[(size_t)grow * DIM + col] = v;
            }
        }
}

// ============================ launch =========================================
extern "C" void kernel_launch(void* const* d_in, const int* in_sizes, int n_in,
                              void* d_out, int out_size) {
    const float* c1 = (const float*)d_in[0];
    const float* c2 = (const float*)d_in[1];
    const unsigned char* cmask = (const unsigned char*)d_in[2];
    const float* Wf = (const float*)d_in[3];
    const float* bf = (const float*)d_in[4];
    const float* Wg = (const float*)d_in[5];
    const float* bg = (const float*)d_in[6];
    float* out = (float*)d_out;

    cudaFuncSetAttribute(k_gemm_scores, cudaFuncAttributeMaxDynamicSharedMemorySize, SMEM_DYN);
    cudaFuncSetAttribute(k_gemm_aug,    cudaFuncAttributeMaxDynamicSharedMemorySize, SMEM_DYN);
    cudaFuncSetAttribute(k_gemm_fusion, cudaFuncAttributeMaxDynamicSharedMemorySize, SMEM_DYN);

    k_prep_split<<<(BATCH * LSEQ * DIM / 2) / 256, 256>>>(c1, c2);
    k_prep_t<<<dim3(LSEQ / 64, DIM / 32, BATCH), dim3(32, 8)>>>(c1);
    k_prep_wft<<<(DIM * 4 * DIM) / 256, 256>>>(Wf);

    k_gemm_scores<<<dim3(NJT, LSEQ / 128, BATCH), 256, SMEM_DYN>>>(cmask);
    k_reduce_invS<<<(BATCH * LSEQ) / 256, 256>>>();
    k_gemm_aug<<<dim3(DIM / 128, LSEQ / 128, BATCH), 256, SMEM_DYN>>>(c2, Wg);
    k_gemm_fusion<<<dim3(DIM / 128, (BATCH * LSEQ) / 128), 256, SMEM_DYN>>>(c2, bf, bg, out);
}

// round 13
// speedup vs baseline: 1.7988x; 1.1050x over previous
#include <cuda_runtime.h>
#include <cuda_bf16.h>
#include <cstdint>
#include <math.h>

#define LSEQ 2048
#define DIM  256
#define BATCH 8
#define NJT2 (LSEQ / 64)       // 32 j-tiles per row (64-wide)

#define KC 32
#define PAD_STR 40
#define TILE_A_B (128 * PAD_STR * 2)   // 10240 B (128-row tile)
#define TILE_B_B (64 * PAD_STR * 2)    // 5120 B  (64-row tile)
#define OFF_AH 0
#define OFF_AL TILE_A_B
#define OFF_BH (2 * TILE_A_B)
#define OFF_BL (2 * TILE_A_B + TILE_B_B)
#define STAGE_B (2 * TILE_A_B + 2 * TILE_B_B)  // 30720
#define SMEM_DYN (2 * STAGE_B)                  // 61440
#define NTHR 128

#define EXP_SHIFT 80.0f

// ============================ PTX helpers ====================================
__device__ __forceinline__ uint32_t smem_to_u32(const void* p) {
    uint32_t a;
    asm("{ .reg .u64 t; cvta.to.shared.u64 t, %1; cvt.u32.u64 %0, t; }"
        : "=r"(a) : "l"(p));
    return a;
}
__device__ __forceinline__ void cp_async16(uint32_t dst, const void* src) {
    asm volatile("cp.async.cg.shared.global [%0], [%1], 16;" :: "r"(dst), "l"(src));
}
#define CP_COMMIT() asm volatile("cp.async.commit_group;" ::: "memory")
#define CP_WAIT0()  asm volatile("cp.async.wait_group 0;" ::: "memory")
#define CP_WAIT1()  asm volatile("cp.async.wait_group 1;" ::: "memory")

__device__ __forceinline__ void ldsm_x4(uint32_t addr, uint32_t* r) {
    asm volatile("ldmatrix.sync.aligned.m8n8.x4.shared.b16 {%0,%1,%2,%3}, [%4];"
                 : "=r"(r[0]), "=r"(r[1]), "=r"(r[2]), "=r"(r[3]) : "r"(addr));
}
__device__ __forceinline__ void mma_bf16(float* c, const uint32_t* a, const uint32_t* b) {
    asm("mma.sync.aligned.m16n8k16.row.col.f32.bf16.bf16.f32 "
        "{%0,%1,%2,%3}, {%4,%5,%6,%7}, {%8,%9}, {%0,%1,%2,%3};"
        : "+f"(c[0]), "+f"(c[1]), "+f"(c[2]), "+f"(c[3])
        : "r"(a[0]), "r"(a[1]), "r"(a[2]), "r"(a[3]), "r"(b[0]), "r"(b[1]));
}

__device__ __forceinline__ void split_pair(float v0, float v1,
                                           __nv_bfloat162& hh, __nv_bfloat162& ll) {
    hh = __floats2bfloat162_rn(v0, v1);
    const float f0 = __bfloat162float(hh.x);
    const float f1 = __bfloat162float(hh.y);
    ll = __floats2bfloat162_rn(v0 - f0, v1 - f1);
}

// ============================ device scratch =================================
static __device__ __nv_bfloat16 g_c1_hi[(size_t)BATCH * LSEQ * DIM];
static __device__ __nv_bfloat16 g_c1_lo[(size_t)BATCH * LSEQ * DIM];
static __device__ __nv_bfloat16 g_c2_hi[(size_t)BATCH * LSEQ * DIM];
static __device__ __nv_bfloat16 g_c2_lo[(size_t)BATCH * LSEQ * DIM];
static __device__ __nv_bfloat16 g_c1t_hi[(size_t)BATCH * DIM * LSEQ];
static __device__ __nv_bfloat16 g_c1t_lo[(size_t)BATCH * DIM * LSEQ];
static __device__ __nv_bfloat16 g_wft_hi[(size_t)DIM * 4 * DIM];
static __device__ __nv_bfloat16 g_alpha_hi[(size_t)BATCH * LSEQ * LSEQ];
static __device__ __nv_bfloat16 g_alpha_lo[(size_t)BATCH * LSEQ * LSEQ];
static __device__ float         g_psum[(size_t)BATCH * LSEQ * NJT2];
static __device__ float         g_invS[BATCH * LSEQ];
static __device__ __nv_bfloat16 g_z_hi[(size_t)BATCH * LSEQ * 4 * DIM];
static __device__ __nv_bfloat16 g_z_lo[(size_t)BATCH * LSEQ * 4 * DIM];
static __device__ float         g_gateP[BATCH * LSEQ * 4];

// ============================ prep kernels ===================================
__global__ __launch_bounds__(256) void k_prep_split(const float* __restrict__ c1,
                                                    const float* __restrict__ c2) {
    const size_t p = (size_t)blockIdx.x * 256 + threadIdx.x;
    if (p < (size_t)BATCH * LSEQ * DIM / 2) {
        const float2 v1 = ((const float2*)c1)[p];
        const float2 v2 = ((const float2*)c2)[p];
        __nv_bfloat162 hh, ll;
        split_pair(v1.x, v1.y, hh, ll);
        ((__nv_bfloat162*)g_c1_hi)[p] = hh;
        ((__nv_bfloat162*)g_c1_lo)[p] = ll;
        split_pair(v2.x, v2.y, hh, ll);
        ((__nv_bfloat162*)g_c2_hi)[p] = hh;
        ((__nv_bfloat162*)g_c2_lo)[p] = ll;
    }
}

__global__ __launch_bounds__(256) void k_prep_t(const float* __restrict__ c1) {
    __shared__ float tile[64][33];
    const int b = blockIdx.z;
    const int j0 = blockIdx.x * 64, d0 = blockIdx.y * 32;
    const float* src = c1 + (size_t)b * LSEQ * DIM;
    const int tx = threadIdx.x, ty = threadIdx.y;
#pragma unroll
    for (int r = 0; r < 64; r += 8)
        tile[ty + r][tx] = src[(size_t)(j0 + ty + r) * DIM + d0 + tx];
    __syncthreads();
#pragma unroll
    for (int r = 0; r < 32; r += 8) {
        const int d = ty + r;
        const float v0 = tile[2 * tx][d];
        const float v1 = tile[2 * tx + 1][d];
        __nv_bfloat162 hh, ll;
        split_pair(v0, v1, hh, ll);
        const size_t o = (size_t)b * DIM * LSEQ + (size_t)(d0 + d) * LSEQ + j0 + 2 * tx;
        *(__nv_bfloat162*)&g_c1t_hi[o] = hh;
        *(__nv_bfloat162*)&g_c1t_lo[o] = ll;
    }
}

__global__ __launch_bounds__(256) void k_prep_wft(const float* __restrict__ Wf) {
    int i = blockIdx.x * 256 + threadIdx.x;
    if (i < DIM * 4 * DIM) {
        int n = i >> 10, k = i & 1023;
        g_wft_hi[i] = __float2bfloat16(Wf[(size_t)k * DIM + n]);
    }
}

// ============================ HMMA GEMM mainloop =============================
// Block tile 128x64, 4 warps (2m x 2n), warp tile 64x32, 2-stage cp.async.
template <bool TWO_PASS>
__device__ __forceinline__ void load_chunk(uint32_t sbase,
                                           const __nv_bfloat16* __restrict__ Ah,
                                           const __nv_bfloat16* __restrict__ Al,
                                           size_t aStr,
                                           const __nv_bfloat16* __restrict__ Bh,
                                           const __nv_bfloat16* __restrict__ Bl,
                                           size_t bStr, int kOff) {
    const int t = threadIdx.x;
    const int c = (t & 3) * 8;   // bf16 col
    const int r = t >> 2;        // 0..31
    const uint32_t soff = (uint32_t)(r * PAD_STR + c) * 2;
    const uint32_t rstep = 32 * PAD_STR * 2;
    {
        const __nv_bfloat16* g = Ah + (size_t)r * aStr + kOff + c;
#pragma unroll
        for (int q = 0; q < 4; q++)
            cp_async16(sbase + OFF_AH + soff + q * rstep, g + (size_t)(32 * q) * aStr);
    }
    {
        const __nv_bfloat16* g = Al + (size_t)r * aStr + kOff + c;
#pragma unroll
        for (int q = 0; q < 4; q++)
            cp_async16(sbase + OFF_AL + soff + q * rstep, g + (size_t)(32 * q) * aStr);
    }
    {
        const __nv_bfloat16* g = Bh + (size_t)r * bStr + kOff + c;
        cp_async16(sbase + OFF_BH + soff, g);
        cp_async16(sbase + OFF_BH + soff + rstep, g + (size_t)32 * bStr);
    }
    if (!TWO_PASS) {
        const __nv_bfloat16* g = Bl + (size_t)r * bStr + kOff + c;
        cp_async16(sbase + OFF_BL + soff, g);
        cp_async16(sbase + OFF_BL + soff + rstep, g + (size_t)32 * bStr);
    }
}

template <bool TWO_PASS>
__device__ __forceinline__ void gemm_tile(const __nv_bfloat16* __restrict__ Ah,
                                          const __nv_bfloat16* __restrict__ Al,
                                          size_t aStr,
                                          const __nv_bfloat16* __restrict__ Bh,
                                          const __nv_bfloat16* __restrict__ Bl,
                                          size_t bStr, int nChunks, char* sm,
                                          float acc[4][4][4]) {
    const int t = threadIdx.x;
    const int w = t >> 5, lane = t & 31;
    const int wm = (w & 1) * 64;
    const int wn = (w >> 1) * 32;
    const uint32_t smb = smem_to_u32(sm);

#pragma unroll
    for (int mf = 0; mf < 4; mf++)
#pragma unroll
        for (int nf = 0; nf < 4; nf++)
#pragma unroll
            for (int e = 0; e < 4; e++) acc[mf][nf][e] = 0.f;

    const int arow = wm + (lane & 15);
    const int acol = (lane >> 4) * 8;
    const int brow = wn + (lane & 7) + ((lane >> 4) ? 8 : 0);
    const int bcol = ((lane >> 3) & 1) * 8;

    load_chunk<TWO_PASS>(smb, Ah, Al, aStr, Bh, Bl, bStr, 0);
    CP_COMMIT();

    int cur = 0;
    for (int kc = 0; kc < nChunks; kc++) {
        if (kc + 1 < nChunks) {
            load_chunk<TWO_PASS>(smb + (uint32_t)(1 - cur) * STAGE_B, Ah, Al, aStr,
                                 Bh, Bl, bStr, (kc + 1) * KC);
            CP_COMMIT();
            CP_WAIT1();
        } else {
            CP_WAIT0();
        }
        __syncthreads();

        const uint32_t s = (uint32_t)cur * STAGE_B;
        const uint32_t sah = smb + s + OFF_AH;
        const uint32_t sal = smb + s + OFF_AL;
        const uint32_t sbh = smb + s + OFF_BH;
        const uint32_t sbl = smb + s + OFF_BL;

#pragma unroll
        for (int ks = 0; ks < 2; ks++) {
            const int k0 = ks * 16;
            uint32_t ah[4][4], al[4][4], bh[2][4], bl[2][4];
#pragma unroll
            for (int mf = 0; mf < 4; mf++) {
                const uint32_t off = (uint32_t)((arow + mf * 16) * PAD_STR + acol + k0) * 2;
                ldsm_x4(sah + off, ah[mf]);
                ldsm_x4(sal + off, al[mf]);
            }
#pragma unroll
            for (int nb = 0; nb < 2; nb++) {
                const uint32_t off = (uint32_t)((brow + nb * 16) * PAD_STR + bcol + k0) * 2;
                ldsm_x4(sbh + off, bh[nb]);
                if (!TWO_PASS) ldsm_x4(sbl + off, bl[nb]);
            }
            const int NP = TWO_PASS ? 2 : 3;
#pragma unroll
            for (int p = 0; p < NP; p++)
#pragma unroll
                for (int mf = 0; mf < 4; mf++)
#pragma unroll
                    for (int nf = 0; nf < 4; nf++) {
                        const uint32_t* aa;
                        const uint32_t* bb;
                        if (TWO_PASS) {
                            aa = (p == 1) ? al[mf] : ah[mf];
                            bb = &bh[nf >> 1][(nf & 1) * 2];
                        } else {
                            aa = (p == 2) ? al[mf] : ah[mf];
                            bb = (p == 1) ? &bl[nf >> 1][(nf & 1) * 2]
                                          : &bh[nf >> 1][(nf & 1) * 2];
                        }
                        mma_bf16(acc[mf][nf], aa, bb);
                    }
        }
        __syncthreads();
        cur ^= 1;
    }
}

// ============================ scores kernel ==================================
__global__ __launch_bounds__(NTHR, 3) void k_gemm_scores(const unsigned char* __restrict__ cmask) {
    extern __shared__ char sm[];
    const int b = blockIdx.z, i0 = blockIdx.y * 128, j0 = blockIdx.x * 64;
    const size_t aBase = ((size_t)b * LSEQ + i0) * DIM;
    const size_t bBase = ((size_t)b * LSEQ + j0) * DIM;
    float acc[4][4][4];
    gemm_tile<false>(g_c2_hi + aBase, g_c2_lo + aBase, DIM,
                     g_c1_hi + bBase, g_c1_lo + bBase, DIM, DIM / KC, sm, acc);

    const int t = threadIdx.x;
    const int w = t >> 5, lane = t & 31;
    const int wm = (w & 1) * 64, wn = (w >> 1) * 32;
    const bool diagTile = ((int)(blockIdx.x >> 1) == (int)blockIdx.y);

    float rsum[4][2];
#pragma unroll
    for (int mf = 0; mf < 4; mf++) { rsum[mf][0] = 0.f; rsum[mf][1] = 0.f; }

#pragma unroll
    for (int mf = 0; mf < 4; mf++)
#pragma unroll
        for (int nf = 0; nf < 4; nf++) {
            const int gj = j0 + wn + nf * 8 + (lane & 3) * 2;
            const unsigned char mk0 = cmask[b * LSEQ + gj];
            const unsigned char mk1 = cmask[b * LSEQ + gj + 1];
#pragma unroll
            for (int half = 0; half < 2; half++) {
                const int gi = i0 + wm + mf * 16 + (lane >> 2) + half * 8;
                float e0 = __expf(acc[mf][nf][2 * half] - EXP_SHIFT);
                float e1 = __expf(acc[mf][nf][2 * half + 1] - EXP_SHIFT);
                if (mk0 || (diagTile && gi == gj)) e0 = 0.f;
                if (mk1 || (diagTile && gi == gj + 1)) e1 = 0.f;
                __nv_bfloat162 hh, ll;
                split_pair(e0, e1, hh, ll);
                const size_t o = ((size_t)(b * LSEQ) + gi) * LSEQ + gj;
                *(__nv_bfloat162*)&g_alpha_hi[o] = hh;
                *(__nv_bfloat162*)&g_alpha_lo[o] = ll;
                rsum[mf][half] += e0 + e1;
            }
        }

    float* sred = (float*)sm;   // 256 floats; pipeline smem free post-sync
#pragma unroll
    for (int mf = 0; mf < 4; mf++)
#pragma unroll
        for (int half = 0; half < 2; half++) {
            float r = rsum[mf][half];
            r += __shfl_xor_sync(0xffffffffu, r, 1);
            r += __shfl_xor_sync(0xffffffffu, r, 2);
            if ((lane & 3) == 0) {
                const int rowl = wm + mf * 16 + (lane >> 2) + half * 8;
                sred[(w >> 1) * 128 + rowl] = r;
            }
        }
    __syncthreads();
    {
        const float S = sred[t] + sred[128 + t];
        g_psum[((size_t)(b * LSEQ) + i0 + t) * NJT2 + blockIdx.x] = S;
    }
}

// ============================ invS reduce ====================================
__global__ __launch_bounds__(256) void k_reduce_invS() {
    const int row = blockIdx.x * 256 + threadIdx.x;
    const float4* p = (const float4*)(g_psum + (size_t)row * NJT2);
    float S = 0.f;
#pragma unroll
    for (int q = 0; q < NJT2 / 4; q++) {
        const float4 v = p[q];
        S += (v.x + v.y) + (v.z + v.w);
    }
    g_invS[row] = 1.f / S;
}

// ============================ aug kernel ====================================
__global__ __launch_bounds__(NTHR, 3) void k_gemm_aug(const float* __restrict__ c2,
                                                      const float* __restrict__ Wg) {
    extern __shared__ char sm[];
    const int b = blockIdx.z, i0 = blockIdx.y * 128, n0 = blockIdx.x * 64;
    const size_t aBase = ((size_t)b * LSEQ + i0) * LSEQ;
    const size_t bBase = ((size_t)b * DIM + n0) * LSEQ;
    float acc[4][4][4];
    gemm_tile<false>(g_alpha_hi + aBase, g_alpha_lo + aBase, LSEQ,
                     g_c1t_hi + bBase, g_c1t_lo + bBase, LSEQ, LSEQ / KC, sm, acc);

    const int t = threadIdx.x;
    const int w = t >> 5, lane = t & 31;
    const int wm = (w & 1) * 64, wn = (w >> 1) * 32;

    float gsum[4][2];
#pragma unroll
    for (int mf = 0; mf < 4; mf++) { gsum[mf][0] = 0.f; gsum[mf][1] = 0.f; }

#pragma unroll
    for (int mf = 0; mf < 4; mf++)
#pragma unroll
        for (int half = 0; half < 2; half++) {
            const int gi = i0 + wm + mf * 16 + (lane >> 2) + half * 8;
            const size_t grow = (size_t)(b * LSEQ) + gi;
            const float invS = g_invS[grow];
#pragma unroll
            for (int nf = 0; nf < 4; nf++) {
                const int gn = n0 + wn + nf * 8 + (lane & 3) * 2;
                const float a0 = acc[mf][nf][2 * half] * invS;
                const float a1 = acc[mf][nf][2 * half + 1] * invS;
                const float2 cv = *(const float2*)&c2[grow * DIM + gn];
                const float z0[4] = {cv.x, a0, cv.x * a0, cv.x - a0};
                const float z1[4] = {cv.y, a1, cv.y * a1, cv.y - a1};
#pragma unroll
                for (int s = 0; s < 4; s++) {
                    const int col = s * DIM + gn;
                    __nv_bfloat162 hh, ll;
                    split_pair(z0[s], z1[s], hh, ll);
                    const size_t o = grow * (4 * DIM) + col;
                    *(__nv_bfloat162*)&g_z_hi[o] = hh;
                    *(__nv_bfloat162*)&g_z_lo[o] = ll;
                    gsum[mf][half] += z0[s] * Wg[col] + z1[s] * Wg[col + 1];
                }
            }
        }

    float* sred = (float*)sm;
#pragma unroll
    for (int mf = 0; mf < 4; mf++)
#pragma unroll
        for (int half = 0; half < 2; half++) {
            float r = gsum[mf][half];
            r += __shfl_xor_sync(0xffffffffu, r, 1);
            r += __shfl_xor_sync(0xffffffffu, r, 2);
            if ((lane & 3) == 0) {
                const int rowl = wm + mf * 16 + (lane >> 2) + half * 8;
                sred[(w >> 1) * 128 + rowl] = r;
            }
        }
    __syncthreads();
    {
        const float gp = sred[t] + sred[128 + t];
        g_gateP[((size_t)(b * LSEQ) + i0 + t) * 4 + blockIdx.x] = gp;
    }
}

// ============================ fusion kernel ==================================
__global__ __launch_bounds__(NTHR, 3) void k_gemm_fusion(const float* __restrict__ c2,
                                                         const float* __restrict__ bf,
                                                         const float* __restrict__ bg,
                                                         float* __restrict__ out) {
    extern __shared__ char sm[];
    const int n0 = blockIdx.x * 64, m0 = blockIdx.y * 128;
    const size_t aBase = (size_t)m0 * (4 * DIM);
    const size_t bBase = (size_t)n0 * (4 * DIM);
    float acc[4][4][4];
    gemm_tile<true>(g_z_hi + aBase, g_z_lo + aBase, 4 * DIM,
                    g_wft_hi + bBase, g_wft_hi + bBase, 4 * DIM, (4 * DIM) / KC, sm, acc);

    const int w = threadIdx.x >> 5, lane = threadIdx.x & 31;
    const int wm = (w & 1) * 64, wn = (w >> 1) * 32;
    const float bgv = bg[0];
#pragma unroll
    for (int mf = 0; mf < 4; mf++)
#pragma unroll
        for (int half = 0; half < 2; half++) {
            const int grow = m0 + wm + mf * 16 + (lane >> 2) + half * 8;
            const float4 gp4 = *(const float4*)&g_gateP[(size_t)grow * 4];
            const float gp = (gp4.x + gp4.y) + (gp4.z + gp4.w);
            const float g = 1.f / (1.f + __expf(-(gp + bgv)));
#pragma unroll
            for (int nf = 0; nf < 4; nf++) {
                const int col = n0 + wn + nf * 8 + (lane & 3) * 2;
                const float bf0 = bf[col], bf1 = bf[col + 1];
                const float2 cv = *(const float2*)&c2[(size_t)grow * DIM + col];
                float2 v;
                v.x = g * tanhf(acc[mf][nf][2 * half] + bf0) + (1.f - g) * cv.x;
                v.y = g * tanhf(acc[mf][nf][2 * half + 1] + bf1) + (1.f - g) * cv.y;
                *(float2*)&out[(size_t)grow * DIM + col] = v;
            }
        }
}

// ============================ launch =========================================
extern "C" void kernel_launch(void* const* d_in, const int* in_sizes, int n_in,
                              void* d_out, int out_size) {
    const float* c1 = (const float*)d_in[0];
    const float* c2 = (const float*)d_in[1];
    const unsigned char* cmask = (const unsigned char*)d_in[2];
    const float* Wf = (const float*)d_in[3];
    const float* bf = (const float*)d_in[4];
    const float* Wg = (const float*)d_in[5];
    const float* bg = (const float*)d_in[6];
    float* out = (float*)d_out;

    cudaFuncSetAttribute(k_gemm_scores, cudaFuncAttributeMaxDynamicSharedMemorySize, SMEM_DYN);
    cudaFuncSetAttribute(k_gemm_aug,    cudaFuncAttributeMaxDynamicSharedMemorySize, SMEM_DYN);
    cudaFuncSetAttribute(k_gemm_fusion, cudaFuncAttributeMaxDynamicSharedMemorySize, SMEM_DYN);

    k_prep_split<<<(BATCH * LSEQ * DIM / 2) / 256, 256>>>(c1, c2);
    k_prep_t<<<dim3(LSEQ / 64, DIM / 32, BATCH), dim3(32, 8)>>>(c1);
    k_prep_wft<<<(DIM * 4 * DIM) / 256, 256>>>(Wf);

    k_gemm_scores<<<dim3(NJT2, LSEQ / 128, BATCH), NTHR, SMEM_DYN>>>(cmask);
    k_reduce_invS<<<(BATCH * LSEQ) / 256, 256>>>();
    k_gemm_aug<<<dim3(DIM / 64, LSEQ / 128, BATCH), NTHR, SMEM_DYN>>>(c2, Wg);
    k_gemm_fusion<<<dim3(DIM / 64, (BATCH * LSEQ) / 128), NTHR, SMEM_DYN>>>(c2, bf, bg, out);
}

// round 14
// speedup vs baseline: 2.2123x; 1.2299x over previous
#include <cuda_runtime.h>
#include <cuda_bf16.h>
#include <cstdint>
#include <math.h>

#define LSEQ 2048
#define DIM  256
#define BATCH 8
#define NJT2 (LSEQ / 64)       // 32 j-tiles per row (64-wide)

#define KC 32
// XOR-swizzled smem: exact 64B rows, no padding.
#define ROW_B 64
#define TILE_A_B (128 * ROW_B)         // 8192
#define TILE_B_B (64 * ROW_B)          // 4096
#define OFF_AH 0
#define OFF_AL TILE_A_B
#define OFF_BH (2 * TILE_A_B)
#define OFF_BL (2 * TILE_A_B + TILE_B_B)
#define STAGE_B (2 * TILE_A_B + 2 * TILE_B_B)  // 24576
#define SMEM_DYN (2 * STAGE_B)                  // 49152
#define NTHR 128

#define EXP_SHIFT 80.0f

// ============================ PTX helpers ====================================
__device__ __forceinline__ uint32_t smem_to_u32(const void* p) {
    uint32_t a;
    asm("{ .reg .u64 t; cvta.to.shared.u64 t, %1; cvt.u32.u64 %0, t; }"
        : "=r"(a) : "l"(p));
    return a;
}
__device__ __forceinline__ void cp_async16(uint32_t dst, const void* src) {
    asm volatile("cp.async.cg.shared.global [%0], [%1], 16;" :: "r"(dst), "l"(src));
}
#define CP_COMMIT() asm volatile("cp.async.commit_group;" ::: "memory")
#define CP_WAIT0()  asm volatile("cp.async.wait_group 0;" ::: "memory")
#define CP_WAIT1()  asm volatile("cp.async.wait_group 1;" ::: "memory")

__device__ __forceinline__ void ldsm_x4(uint32_t addr, uint32_t* r) {
    asm volatile("ldmatrix.sync.aligned.m8n8.x4.shared.b16 {%0,%1,%2,%3}, [%4];"
                 : "=r"(r[0]), "=r"(r[1]), "=r"(r[2]), "=r"(r[3]) : "r"(addr));
}
__device__ __forceinline__ void mma_bf16(float* c, const uint32_t* a, const uint32_t* b) {
    asm("mma.sync.aligned.m16n8k16.row.col.f32.bf16.bf16.f32 "
        "{%0,%1,%2,%3}, {%4,%5,%6,%7}, {%8,%9}, {%0,%1,%2,%3};"
        : "+f"(c[0]), "+f"(c[1]), "+f"(c[2]), "+f"(c[3])
        : "r"(a[0]), "r"(a[1]), "r"(a[2]), "r"(a[3]), "r"(b[0]), "r"(b[1]));
}

__device__ __forceinline__ void split_pair(float v0, float v1,
                                           __nv_bfloat162& hh, __nv_bfloat162& ll) {
    hh = __floats2bfloat162_rn(v0, v1);
    const float f0 = __bfloat162float(hh.x);
    const float f1 = __bfloat162float(hh.y);
    ll = __floats2bfloat162_rn(v0 - f0, v1 - f1);
}

// swizzled byte offset within a tile: row r (64B rows), column byte cb (16-aligned)
__device__ __forceinline__ uint32_t sw_off(int r, int cb) {
    return (uint32_t)(r * ROW_B + (cb ^ (((r >> 1) & 3) << 4)));
}

// ============================ device scratch =================================
static __device__ __nv_bfloat16 g_c1_hi[(size_t)BATCH * LSEQ * DIM];
static __device__ __nv_bfloat16 g_c1_lo[(size_t)BATCH * LSEQ * DIM];
static __device__ __nv_bfloat16 g_c2_hi[(size_t)BATCH * LSEQ * DIM];
static __device__ __nv_bfloat16 g_c2_lo[(size_t)BATCH * LSEQ * DIM];
static __device__ __nv_bfloat16 g_c1t_hi[(size_t)BATCH * DIM * LSEQ];
static __device__ __nv_bfloat16 g_c1t_lo[(size_t)BATCH * DIM * LSEQ];
static __device__ __nv_bfloat16 g_wft_hi[(size_t)DIM * 4 * DIM];
static __device__ __nv_bfloat16 g_alpha_hi[(size_t)BATCH * LSEQ * LSEQ];
static __device__ __nv_bfloat16 g_alpha_lo[(size_t)BATCH * LSEQ * LSEQ];
static __device__ float         g_psum[(size_t)BATCH * LSEQ * NJT2];
static __device__ float         g_invS[BATCH * LSEQ];
static __device__ __nv_bfloat16 g_z_hi[(size_t)BATCH * LSEQ * 4 * DIM];
static __device__ __nv_bfloat16 g_z_lo[(size_t)BATCH * LSEQ * 4 * DIM];
static __device__ float         g_gateP[BATCH * LSEQ * 4];

// ============================ prep kernels ===================================
__global__ __launch_bounds__(256) void k_prep_split(const float* __restrict__ c1,
                                                    const float* __restrict__ c2) {
    const size_t p = (size_t)blockIdx.x * 256 + threadIdx.x;
    if (p < (size_t)BATCH * LSEQ * DIM / 2) {
        const float2 v1 = ((const float2*)c1)[p];
        const float2 v2 = ((const float2*)c2)[p];
        __nv_bfloat162 hh, ll;
        split_pair(v1.x, v1.y, hh, ll);
        ((__nv_bfloat162*)g_c1_hi)[p] = hh;
        ((__nv_bfloat162*)g_c1_lo)[p] = ll;
        split_pair(v2.x, v2.y, hh, ll);
        ((__nv_bfloat162*)g_c2_hi)[p] = hh;
        ((__nv_bfloat162*)g_c2_lo)[p] = ll;
    }
}

__global__ __launch_bounds__(256) void k_prep_t(const float* __restrict__ c1) {
    __shared__ float tile[64][33];
    const int b = blockIdx.z;
    const int j0 = blockIdx.x * 64, d0 = blockIdx.y * 32;
    const float* src = c1 + (size_t)b * LSEQ * DIM;
    const int tx = threadIdx.x, ty = threadIdx.y;
#pragma unroll
    for (int r = 0; r < 64; r += 8)
        tile[ty + r][tx] = src[(size_t)(j0 + ty + r) * DIM + d0 + tx];
    __syncthreads();
#pragma unroll
    for (int r = 0; r < 32; r += 8) {
        const int d = ty + r;
        const float v0 = tile[2 * tx][d];
        const float v1 = tile[2 * tx + 1][d];
        __nv_bfloat162 hh, ll;
        split_pair(v0, v1, hh, ll);
        const size_t o = (size_t)b * DIM * LSEQ + (size_t)(d0 + d) * LSEQ + j0 + 2 * tx;
        *(__nv_bfloat162*)&g_c1t_hi[o] = hh;
        *(__nv_bfloat162*)&g_c1t_lo[o] = ll;
    }
}

__global__ __launch_bounds__(256) void k_prep_wft(const float* __restrict__ Wf) {
    int i = blockIdx.x * 256 + threadIdx.x;
    if (i < DIM * 4 * DIM) {
        int n = i >> 10, k = i & 1023;
        g_wft_hi[i] = __float2bfloat16(Wf[(size_t)k * DIM + n]);
    }
}

// ============================ HMMA GEMM mainloop =============================
// Block tile 128x64, 4 warps (2m x 2n), warp tile 64x32, 2-stage cp.async,
// XOR-swizzled 64B-row smem.
template <bool TWO_PASS>
__device__ __forceinline__ void load_chunk(uint32_t sbase,
                                           const __nv_bfloat16* __restrict__ Ah,
                                           const __nv_bfloat16* __restrict__ Al,
                                           size_t aStr,
                                           const __nv_bfloat16* __restrict__ Bh,
                                           const __nv_bfloat16* __restrict__ Bl,
                                           size_t bStr, int kOff) {
    const int t = threadIdx.x;
    const int cb = (t & 3) * 16;  // byte col within 64B row
    const int r = t >> 2;         // 0..31
    const int ce = cb >> 1;       // element col
    {
        const __nv_bfloat16* g = Ah + (size_t)r * aStr + kOff + ce;
#pragma unroll
        for (int q = 0; q < 4; q++)
            cp_async16(sbase + OFF_AH + sw_off(r + 32 * q, cb), g + (size_t)(32 * q) * aStr);
    }
    {
        const __nv_bfloat16* g = Al + (size_t)r * aStr + kOff + ce;
#pragma unroll
        for (int q = 0; q < 4; q++)
            cp_async16(sbase + OFF_AL + sw_off(r + 32 * q, cb), g + (size_t)(32 * q) * aStr);
    }
    {
        const __nv_bfloat16* g = Bh + (size_t)r * bStr + kOff + ce;
        cp_async16(sbase + OFF_BH + sw_off(r, cb), g);
        cp_async16(sbase + OFF_BH + sw_off(r + 32, cb), g + (size_t)32 * bStr);
    }
    if (!TWO_PASS) {
        const __nv_bfloat16* g = Bl + (size_t)r * bStr + kOff + ce;
        cp_async16(sbase + OFF_BL + sw_off(r, cb), g);
        cp_async16(sbase + OFF_BL + sw_off(r + 32, cb), g + (size_t)32 * bStr);
    }
}

template <bool TWO_PASS>
__device__ __forceinline__ void gemm_tile(const __nv_bfloat16* __restrict__ Ah,
                                          const __nv_bfloat16* __restrict__ Al,
                                          size_t aStr,
                                          const __nv_bfloat16* __restrict__ Bh,
                                          const __nv_bfloat16* __restrict__ Bl,
                                          size_t bStr, int nChunks, char* sm,
                                          float acc[4][4][4]) {
    const int t = threadIdx.x;
    const int w = t >> 5, lane = t & 31;
    const int wm = (w & 1) * 64;
    const int wn = (w >> 1) * 32;
    const uint32_t smb = smem_to_u32(sm);

#pragma unroll
    for (int mf = 0; mf < 4; mf++)
#pragma unroll
        for (int nf = 0; nf < 4; nf++)
#pragma unroll
            for (int e = 0; e < 4; e++) acc[mf][nf][e] = 0.f;

    const int arow = wm + (lane & 15);
    const int acb  = (lane >> 4) * 16;          // byte col of A fragment
    const int brow = wn + (lane & 7) + ((lane >> 4) ? 8 : 0);
    const int bcb  = ((lane >> 3) & 1) * 16;    // byte col of B fragment

    load_chunk<TWO_PASS>(smb, Ah, Al, aStr, Bh, Bl, bStr, 0);
    CP_COMMIT();

    int cur = 0;
    for (int kc = 0; kc < nChunks; kc++) {
        if (kc + 1 < nChunks) {
            load_chunk<TWO_PASS>(smb + (uint32_t)(1 - cur) * STAGE_B, Ah, Al, aStr,
                                 Bh, Bl, bStr, (kc + 1) * KC);
            CP_COMMIT();
            CP_WAIT1();
        } else {
            CP_WAIT0();
        }
        __syncthreads();

        const uint32_t s = (uint32_t)cur * STAGE_B;
        const uint32_t sah = smb + s + OFF_AH;
        const uint32_t sal = smb + s + OFF_AL;
        const uint32_t sbh = smb + s + OFF_BH;
        const uint32_t sbl = smb + s + OFF_BL;

#pragma unroll
        for (int ks = 0; ks < 2; ks++) {
            const int kb = ks * 32;   // byte offset of k-slice
            uint32_t ah[4][4], al[4][4], bh[2][4], bl[2][4];
#pragma unroll
            for (int mf = 0; mf < 4; mf++) {
                const uint32_t off = sw_off(arow + mf * 16, acb + kb);
                ldsm_x4(sah + off, ah[mf]);
                ldsm_x4(sal + off, al[mf]);
            }
#pragma unroll
            for (int nb = 0; nb < 2; nb++) {
                const uint32_t off = sw_off(brow + nb * 16, bcb + kb);
                ldsm_x4(sbh + off, bh[nb]);
                if (!TWO_PASS) ldsm_x4(sbl + off, bl[nb]);
            }
            const int NP = TWO_PASS ? 2 : 3;
#pragma unroll
            for (int p = 0; p < NP; p++)
#pragma unroll
                for (int mf = 0; mf < 4; mf++)
#pragma unroll
                    for (int nf = 0; nf < 4; nf++) {
                        const uint32_t* aa;
                        const uint32_t* bb;
                        if (TWO_PASS) {
                            aa = (p == 1) ? al[mf] : ah[mf];
                            bb = &bh[nf >> 1][(nf & 1) * 2];
                        } else {
                            aa = (p == 2) ? al[mf] : ah[mf];
                            bb = (p == 1) ? &bl[nf >> 1][(nf & 1) * 2]
                                          : &bh[nf >> 1][(nf & 1) * 2];
                        }
                        mma_bf16(acc[mf][nf], aa, bb);
                    }
        }
        __syncthreads();
        cur ^= 1;
    }
}

// ============================ scores kernel ==================================
__global__ __launch_bounds__(NTHR, 4) void k_gemm_scores(const unsigned char* __restrict__ cmask) {
    extern __shared__ char sm[];
    const int b = blockIdx.z, i0 = blockIdx.y * 128, j0 = blockIdx.x * 64;
    const size_t aBase = ((size_t)b * LSEQ + i0) * DIM;
    const size_t bBase = ((size_t)b * LSEQ + j0) * DIM;
    float acc[4][4][4];
    gemm_tile<false>(g_c2_hi + aBase, g_c2_lo + aBase, DIM,
                     g_c1_hi + bBase, g_c1_lo + bBase, DIM, DIM / KC, sm, acc);

    const int t = threadIdx.x;
    const int w = t >> 5, lane = t & 31;
    const int wm = (w & 1) * 64, wn = (w >> 1) * 32;
    const bool diagTile = ((int)(blockIdx.x >> 1) == (int)blockIdx.y);

    float rsum[4][2];
#pragma unroll
    for (int mf = 0; mf < 4; mf++) { rsum[mf][0] = 0.f; rsum[mf][1] = 0.f; }

#pragma unroll
    for (int mf = 0; mf < 4; mf++)
#pragma unroll
        for (int nf = 0; nf < 4; nf++) {
            const int gj = j0 + wn + nf * 8 + (lane & 3) * 2;
            const unsigned char mk0 = cmask[b * LSEQ + gj];
            const unsigned char mk1 = cmask[b * LSEQ + gj + 1];
#pragma unroll
            for (int half = 0; half < 2; half++) {
                const int gi = i0 + wm + mf * 16 + (lane >> 2) + half * 8;
                float e0 = __expf(acc[mf][nf][2 * half] - EXP_SHIFT);
                float e1 = __expf(acc[mf][nf][2 * half + 1] - EXP_SHIFT);
                if (mk0 || (diagTile && gi == gj)) e0 = 0.f;
                if (mk1 || (diagTile && gi == gj + 1)) e1 = 0.f;
                __nv_bfloat162 hh, ll;
                split_pair(e0, e1, hh, ll);
                const size_t o = ((size_t)(b * LSEQ) + gi) * LSEQ + gj;
                *(__nv_bfloat162*)&g_alpha_hi[o] = hh;
                *(__nv_bfloat162*)&g_alpha_lo[o] = ll;
                rsum[mf][half] += e0 + e1;
            }
        }

    float* sred = (float*)sm;
#pragma unroll
    for (int mf = 0; mf < 4; mf++)
#pragma unroll
        for (int half = 0; half < 2; half++) {
            float r = rsum[mf][half];
            r += __shfl_xor_sync(0xffffffffu, r, 1);
            r += __shfl_xor_sync(0xffffffffu, r, 2);
            if ((lane & 3) == 0) {
                const int rowl = wm + mf * 16 + (lane >> 2) + half * 8;
                sred[(w >> 1) * 128 + rowl] = r;
            }
        }
    __syncthreads();
    {
        const float S = sred[t] + sred[128 + t];
        g_psum[((size_t)(b * LSEQ) + i0 + t) * NJT2 + blockIdx.x] = S;
    }
}

// ============================ invS reduce ====================================
__global__ __launch_bounds__(256) void k_reduce_invS() {
    const int row = blockIdx.x * 256 + threadIdx.x;
    const float4* p = (const float4*)(g_psum + (size_t)row * NJT2);
    float S = 0.f;
#pragma unroll
    for (int q = 0; q < NJT2 / 4; q++) {
        const float4 v = p[q];
        S += (v.x + v.y) + (v.z + v.w);
    }
    g_invS[row] = 1.f / S;
}

// ============================ aug kernel ====================================
__global__ __launch_bounds__(NTHR, 4) void k_gemm_aug(const float* __restrict__ c2,
                                                      const float* __restrict__ Wg) {
    extern __shared__ char sm[];
    const int b = blockIdx.z, i0 = blockIdx.y * 128, n0 = blockIdx.x * 64;
    const size_t aBase = ((size_t)b * LSEQ + i0) * LSEQ;
    const size_t bBase = ((size_t)b * DIM + n0) * LSEQ;
    float acc[4][4][4];
    gemm_tile<false>(g_alpha_hi + aBase, g_alpha_lo + aBase, LSEQ,
                     g_c1t_hi + bBase, g_c1t_lo + bBase, LSEQ, LSEQ / KC, sm, acc);

    const int t = threadIdx.x;
    const int w = t >> 5, lane = t & 31;
    const int wm = (w & 1) * 64, wn = (w >> 1) * 32;

    float gsum[4][2];
#pragma unroll
    for (int mf = 0; mf < 4; mf++) { gsum[mf][0] = 0.f; gsum[mf][1] = 0.f; }

#pragma unroll
    for (int mf = 0; mf < 4; mf++)
#pragma unroll
        for (int half = 0; half < 2; half++) {
            const int gi = i0 + wm + mf * 16 + (lane >> 2) + half * 8;
            const size_t grow = (size_t)(b * LSEQ) + gi;
            const float invS = g_invS[grow];
#pragma unroll
            for (int nf = 0; nf < 4; nf++) {
                const int gn = n0 + wn + nf * 8 + (lane & 3) * 2;
                const float a0 = acc[mf][nf][2 * half] * invS;
                const float a1 = acc[mf][nf][2 * half + 1] * invS;
                const float2 cv = *(const float2*)&c2[grow * DIM + gn];
                const float z0[4] = {cv.x, a0, cv.x * a0, cv.x - a0};
                const float z1[4] = {cv.y, a1, cv.y * a1, cv.y - a1};
#pragma unroll
                for (int s = 0; s < 4; s++) {
                    const int col = s * DIM + gn;
                    __nv_bfloat162 hh, ll;
                    split_pair(z0[s], z1[s], hh, ll);
                    const size_t o = grow * (4 * DIM) + col;
                    *(__nv_bfloat162*)&g_z_hi[o] = hh;
                    *(__nv_bfloat162*)&g_z_lo[o] = ll;
                    gsum[mf][half] += z0[s] * Wg[col] + z1[s] * Wg[col + 1];
                }
            }
        }

    float* sred = (float*)sm;
#pragma unroll
    for (int mf = 0; mf < 4; mf++)
#pragma unroll
        for (int half = 0; half < 2; half++) {
            float r = gsum[mf][half];
            r += __shfl_xor_sync(0xffffffffu, r, 1);
            r += __shfl_xor_sync(0xffffffffu, r, 2);
            if ((lane & 3) == 0) {
                const int rowl = wm + mf * 16 + (lane >> 2) + half * 8;
                sred[(w >> 1) * 128 + rowl] = r;
            }
        }
    __syncthreads();
    {
        const float gp = sred[t] + sred[128 + t];
        g_gateP[((size_t)(b * LSEQ) + i0 + t) * 4 + blockIdx.x] = gp;
    }
}

// ============================ fusion kernel ==================================
__global__ __launch_bounds__(NTHR, 4) void k_gemm_fusion(const float* __restrict__ c2,
                                                         const float* __restrict__ bf,
                                                         const float* __restrict__ bg,
                                                         float* __restrict__ out) {
    extern __shared__ char sm[];
    const int n0 = blockIdx.x * 64, m0 = blockIdx.y * 128;
    const size_t aBase = (size_t)m0 * (4 * DIM);
    const size_t bBase = (size_t)n0 * (4 * DIM);
    float acc[4][4][4];
    gemm_tile<true>(g_z_hi + aBase, g_z_lo + aBase, 4 * DIM,
                    g_wft_hi + bBase, g_wft_hi + bBase, 4 * DIM, (4 * DIM) / KC, sm, acc);

    const int w = threadIdx.x >> 5, lane = threadIdx.x & 31;
    const int wm = (w & 1) * 64, wn = (w >> 1) * 32;
    const float bgv = bg[0];
#pragma unroll
    for (int mf = 0; mf < 4; mf++)
#pragma unroll
        for (int half = 0; half < 2; half++) {
            const int grow = m0 + wm + mf * 16 + (lane >> 2) + half * 8;
            const float4 gp4 = *(const float4*)&g_gateP[(size_t)grow * 4];
            const float gp = (gp4.x + gp4.y) + (gp4.z + gp4.w);
            const float g = 1.f / (1.f + __expf(-(gp + bgv)));
#pragma unroll
            for (int nf = 0; nf < 4; nf++) {
                const int col = n0 + wn + nf * 8 + (lane & 3) * 2;
                const float bf0 = bf[col], bf1 = bf[col + 1];
                const float2 cv = *(const float2*)&c2[(size_t)grow * DIM + col];
                float2 v;
                v.x = g * tanhf(acc[mf][nf][2 * half] + bf0) + (1.f - g) * cv.x;
                v.y = g * tanhf(acc[mf][nf][2 * half + 1] + bf1) + (1.f - g) * cv.y;
                *(float2*)&out[(size_t)grow * DIM + col] = v;
            }
        }
}

// ============================ launch =========================================
extern "C" void kernel_launch(void* const* d_in, const int* in_sizes, int n_in,
                              void* d_out, int out_size) {
    const float* c1 = (const float*)d_in[0];
    const float* c2 = (const float*)d_in[1];
    const unsigned char* cmask = (const unsigned char*)d_in[2];
    const float* Wf = (const float*)d_in[3];
    const float* bf = (const float*)d_in[4];
    const float* Wg = (const float*)d_in[5];
    const float* bg = (const float*)d_in[6];
    float* out = (float*)d_out;

    cudaFuncSetAttribute(k_gemm_scores, cudaFuncAttributeMaxDynamicSharedMemorySize, SMEM_DYN);
    cudaFuncSetAttribute(k_gemm_aug,    cudaFuncAttributeMaxDynamicSharedMemorySize, SMEM_DYN);
    cudaFuncSetAttribute(k_gemm_fusion, cudaFuncAttributeMaxDynamicSharedMemorySize, SMEM_DYN);

    k_prep_split<<<(BATCH * LSEQ * DIM / 2) / 256, 256>>>(c1, c2);
    k_prep_t<<<dim3(LSEQ / 64, DIM / 32, BATCH), dim3(32, 8)>>>(c1);
    k_prep_wft<<<(DIM * 4 * DIM) / 256, 256>>>(Wf);

    k_gemm_scores<<<dim3(NJT2, LSEQ / 128, BATCH), NTHR, SMEM_DYN>>>(cmask);
    k_reduce_invS<<<(BATCH * LSEQ) / 256, 256>>>();
    k_gemm_aug<<<dim3(DIM / 64, LSEQ / 128, BATCH), NTHR, SMEM_DYN>>>(c2, Wg);
    k_gemm_fusion<<<dim3(DIM / 64, (BATCH * LSEQ) / 128), NTHR, SMEM_DYN>>>(c2, bf, bg, out);
}